// round 3
// baseline (speedup 1.0000x reference)
#include <cuda_runtime.h>

#define NN   50000
#define EE   800000
#define EMB  384

// ---------------- scratch (no allocations allowed) ----------------
__device__ __align__(16) float g_x0[NN * EMB];   // also reused as agg buffer
__device__ __align__(16) float g_x1[NN * EMB];
__device__ __align__(16) float g_h [NN * EMB];
__device__ float g_dinv[NN];
__device__ int   g_deg[NN];
__device__ int   g_is64;      // 1 if edge_index is int64, 0 if int32

__device__ __forceinline__ float leaky(float v) {
    return v > 0.0f ? v : 0.01f * v;
}

// Load edge e's (src, dst) regardless of index dtype.
__device__ __forceinline__ void load_edge(const void* ei, int e, int& src, int& dst) {
    if (g_is64) {
        const long long* p = (const long long*)ei;
        src = (int)p[e];
        dst = (int)p[EE + e];
    } else {
        const int* p = (const int*)ei;
        src = p[e];
        dst = p[EE + e];
    }
}

// ---------------- dtype probe ----------------
// int64 indices are all < NN; int32 pairs reinterpreted as int64 are >= 2^32
// unless the odd word is 0 (prob ~ (1/50000)^64 across 64 samples).
__global__ void detect_idx_dtype(const void* ei) {
    const long long* p = (const long long*)ei;
    int ok64 = 1;
    for (int i = 0; i < 64; i++) {
        long long v = p[i];
        if (v < 0 || v >= NN) { ok64 = 0; break; }
    }
    g_is64 = ok64;
}

// ---------------- generic tiled fp32 GEMM ----------------
// C[M,Nn] = A[M,K] @ B[K,Nn]  (B row-major, ldb = Nn)
// BM=BN=128, BK=16, 256 threads, 8x8 per thread
template<bool LEAKY, bool BIAS, bool SCALE>
__global__ __launch_bounds__(256) void sgemm(
    const float* __restrict__ A, int lda,
    const float* __restrict__ B, int ldb,
    const float* __restrict__ bias,
    float* __restrict__ C, int ldc,
    int M, int Nn, int K)
{
    __shared__ float As[16][128];
    __shared__ float Bs[16][128];

    const int tid = threadIdx.x;
    const int block_row = blockIdx.y * 128;
    const int block_col = blockIdx.x * 128;
    const int tr = tid >> 4;   // 0..15
    const int tc = tid & 15;   // 0..15

    float acc[8][8];
#pragma unroll
    for (int i = 0; i < 8; i++)
#pragma unroll
        for (int j = 0; j < 8; j++) acc[i][j] = 0.0f;

    for (int k0 = 0; k0 < K; k0 += 16) {
        // load A tile: 128 rows x 16 k, float4 along K
#pragma unroll
        for (int i = 0; i < 2; i++) {
            int idx = tid + i * 256;          // 0..511
            int r   = idx >> 2;               // 0..127
            int kk  = (idx & 3) * 4;          // 0,4,8,12
            int grow = block_row + r;
            if (grow >= M) grow = M - 1;      // clamp (stores are predicated)
            float4 av = *(const float4*)(A + (size_t)grow * lda + k0 + kk);
            As[kk + 0][r] = av.x;
            As[kk + 1][r] = av.y;
            As[kk + 2][r] = av.z;
            As[kk + 3][r] = av.w;
        }
        // load B tile: 16 k x 128 n, float4 along N
#pragma unroll
        for (int i = 0; i < 2; i++) {
            int idx = tid + i * 256;
            int kr  = idx >> 5;               // 0..15
            int c   = (idx & 31) * 4;         // 0..124
            float4 bv = *(const float4*)(B + (size_t)(k0 + kr) * ldb + block_col + c);
            *(float4*)&Bs[kr][c] = bv;
        }
        __syncthreads();

#pragma unroll
        for (int kk = 0; kk < 16; kk++) {
            float a[8], b[8];
            float4 a0 = *(const float4*)&As[kk][tr * 4];
            float4 a1 = *(const float4*)&As[kk][64 + tr * 4];
            float4 b0 = *(const float4*)&Bs[kk][tc * 4];
            float4 b1 = *(const float4*)&Bs[kk][64 + tc * 4];
            a[0]=a0.x; a[1]=a0.y; a[2]=a0.z; a[3]=a0.w;
            a[4]=a1.x; a[5]=a1.y; a[6]=a1.z; a[7]=a1.w;
            b[0]=b0.x; b[1]=b0.y; b[2]=b0.z; b[3]=b0.w;
            b[4]=b1.x; b[5]=b1.y; b[6]=b1.z; b[7]=b1.w;
#pragma unroll
            for (int i = 0; i < 8; i++)
#pragma unroll
                for (int j = 0; j < 8; j++)
                    acc[i][j] = fmaf(a[i], b[j], acc[i][j]);
        }
        __syncthreads();
    }

#pragma unroll
    for (int i = 0; i < 8; i++) {
        int r = block_row + ((i < 4) ? tr * 4 + i : 64 + tr * 4 + (i - 4));
        if (r < M) {
            float dv = SCALE ? g_dinv[r] : 1.0f;
#pragma unroll
            for (int j = 0; j < 8; j++) {
                int c = block_col + ((j < 4) ? tc * 4 + j : 64 + tc * 4 + (j - 4));
                float v = acc[i][j];
                if (BIAS)  v += bias[c];
                if (LEAKY) v = leaky(v);
                if (SCALE) v *= dv;
                C[(size_t)r * ldc + c] = v;
            }
        }
    }
}

// ---------------- small front projections (K=4, K=3) ----------------
__global__ void front_small(const float* __restrict__ nump,
                            const float* __restrict__ catp,
                            const float* __restrict__ Wn, const float* __restrict__ bn,
                            const float* __restrict__ Wc, const float* __restrict__ bc)
{
    int node = blockIdx.x;
    int j    = threadIdx.x;   // 0..127
    float n0 = nump[node * 4 + 0], n1 = nump[node * 4 + 1];
    float n2 = nump[node * 4 + 2], n3 = nump[node * 4 + 3];
    float c0 = catp[node * 3 + 0], c1 = catp[node * 3 + 1], c2 = catp[node * 3 + 2];

    float accn = bn[j];
    accn = fmaf(n0, Wn[0 * 128 + j], accn);
    accn = fmaf(n1, Wn[1 * 128 + j], accn);
    accn = fmaf(n2, Wn[2 * 128 + j], accn);
    accn = fmaf(n3, Wn[3 * 128 + j], accn);

    float accc = bc[j];
    accc = fmaf(c0, Wc[0 * 128 + j], accc);
    accc = fmaf(c1, Wc[1 * 128 + j], accc);
    accc = fmaf(c2, Wc[2 * 128 + j], accc);

    g_x0[(size_t)node * EMB + 128 + j] = leaky(accn);
    g_x0[(size_t)node * EMB + 256 + j] = leaky(accc);
}

// ---------------- degree / dinv ----------------
__global__ void zero_deg() {
    int i = blockIdx.x * blockDim.x + threadIdx.x;
    if (i < NN) g_deg[i] = 0;
}

__global__ void deg_count(const void* __restrict__ ei) {
    int e = blockIdx.x * blockDim.x + threadIdx.x;
    if (e < EE) {
        int src, dst;
        load_edge(ei, e, src, dst);
        atomicAdd(&g_deg[dst], 1);
    }
}

__global__ void make_dinv() {
    int i = blockIdx.x * blockDim.x + threadIdx.x;
    if (i < NN) g_dinv[i] = rsqrtf((float)g_deg[i] + 1.0f);
}

// ---------------- zero agg ----------------
__global__ void zero_f4(float4* __restrict__ p, int n4) {
    int i = blockIdx.x * blockDim.x + threadIdx.x;
    if (i < n4) p[i] = make_float4(0.f, 0.f, 0.f, 0.f);
}

// ---------------- edge scatter: agg[dst] += y[src] ----------------
// one warp per edge; 96 float4 per row -> 3 per lane; vector red.v4
__global__ __launch_bounds__(256) void edge_scatter(
    const float* __restrict__ y,
    const void* __restrict__ ei,
    float* __restrict__ agg)
{
    int warp = (blockIdx.x * blockDim.x + threadIdx.x) >> 5;
    int lane = threadIdx.x & 31;
    if (warp >= EE) return;
    int src, dst;
    load_edge(ei, warp, src, dst);
    const float4* ys = (const float4*)(y + (size_t)src * EMB);
    float* ad = agg + (size_t)dst * EMB;
#pragma unroll
    for (int i = 0; i < 3; i++) {
        float4 v = ys[lane + i * 32];
        float* p = ad + (size_t)(lane + i * 32) * 4;
        asm volatile("red.global.add.v4.f32 [%0], {%1,%2,%3,%4};"
                     :: "l"(p), "f"(v.x), "f"(v.y), "f"(v.z), "f"(v.w)
                     : "memory");
    }
}

// ---------------- combine: out = dinv*(agg + y) + b ----------------
__global__ void combine(const float* __restrict__ agg,
                        const float* __restrict__ y,
                        const float* __restrict__ bias,
                        float* __restrict__ out)
{
    int i = blockIdx.x * blockDim.x + threadIdx.x;   // float4 index
    if (i >= NN * (EMB / 4)) return;
    int row  = i / (EMB / 4);
    int colv = i % (EMB / 4);
    float dv = g_dinv[row];
    float4 a = ((const float4*)agg)[i];
    float4 w = ((const float4*)y)[i];
    float4 b = ((const float4*)bias)[colv];
    float4 r;
    r.x = fmaf(dv, a.x + w.x, b.x);
    r.y = fmaf(dv, a.y + w.y, b.y);
    r.z = fmaf(dv, a.z + w.z, b.z);
    r.w = fmaf(dv, a.w + w.w, b.w);
    ((float4*)out)[i] = r;
}

// ---------------- final projection to 2 logits ----------------
__global__ __launch_bounds__(256) void final_proj(
    const float* __restrict__ x,
    const float* __restrict__ W,   // [384,2]
    const float* __restrict__ b,
    float* __restrict__ out)
{
    int warp = (blockIdx.x * blockDim.x + threadIdx.x) >> 5;
    int lane = threadIdx.x & 31;
    if (warp >= NN) return;
    float a0 = 0.f, a1 = 0.f;
    const float* xr = x + (size_t)warp * EMB;
#pragma unroll
    for (int t = 0; t < 12; t++) {
        int k = lane + t * 32;
        float v = xr[k];
        a0 = fmaf(v, W[k * 2 + 0], a0);
        a1 = fmaf(v, W[k * 2 + 1], a1);
    }
#pragma unroll
    for (int off = 16; off > 0; off >>= 1) {
        a0 += __shfl_down_sync(0xffffffffu, a0, off);
        a1 += __shfl_down_sync(0xffffffffu, a1, off);
    }
    if (lane == 0) {
        out[warp * 2 + 0] = a0 + b[0];
        out[warp * 2 + 1] = a1 + b[1];
    }
}

// ---------------- host orchestration ----------------
extern "C" void kernel_launch(void* const* d_in, const int* in_sizes, int n_in,
                              void* d_out, int out_size)
{
    const float* des  = (const float*)d_in[0];
    const float* nump = (const float*)d_in[2];
    const float* catp = (const float*)d_in[3];
    const void*  ei   = d_in[4];
    const float* W_des = (const float*)d_in[5];  const float* b_des = (const float*)d_in[6];
    const float* W_num = (const float*)d_in[7];  const float* b_num = (const float*)d_in[8];
    const float* W_cat = (const float*)d_in[9];  const float* b_cat = (const float*)d_in[10];
    const float* W_in  = (const float*)d_in[11]; const float* b_in  = (const float*)d_in[12];
    const float* W_g1  = (const float*)d_in[13]; const float* b_g1  = (const float*)d_in[14];
    const float* W_g2  = (const float*)d_in[15]; const float* b_g2  = (const float*)d_in[16];
    const float* W_o1  = (const float*)d_in[17]; const float* b_o1  = (const float*)d_in[18];
    const float* W_o2  = (const float*)d_in[19]; const float* b_o2  = (const float*)d_in[20];
    float* out = (float*)d_out;

    float *x0, *x1, *h;
    cudaGetSymbolAddress((void**)&x0, g_x0);
    cudaGetSymbolAddress((void**)&x1, g_x1);
    cudaGetSymbolAddress((void**)&h,  g_h);

    const int MB = (NN + 127) / 128;   // 391 row-blocks
    dim3 blk(256);

    // dtype probe must precede any edge use
    detect_idx_dtype<<<1, 1>>>(ei);

    // degree -> dinv
    zero_deg<<<(NN + 255) / 256, blk>>>();
    deg_count<<<(EE + 255) / 256, blk>>>(ei);
    make_dinv<<<(NN + 255) / 256, blk>>>();

    // front: des proj into x0[:,0:128], small projections into x0[:,128:384]
    sgemm<true, true, false><<<dim3(1, MB), blk>>>(des, 768, W_des, 128, b_des,
                                                   x0, EMB, NN, 128, 768);
    front_small<<<NN, 128>>>(nump, catp, W_num, b_num, W_cat, b_cat);

    // x1 = leaky(x0 @ W_in + b_in)
    sgemm<true, true, false><<<dim3(3, MB), blk>>>(x0, EMB, W_in, EMB, b_in,
                                                   x1, EMB, NN, EMB, EMB);

    // ---- GCN conv 1 ----
    sgemm<false, false, true><<<dim3(3, MB), blk>>>(x1, EMB, W_g1, EMB, nullptr,
                                                    h, EMB, NN, EMB, EMB);   // y = (x1 W) * dinv
    zero_f4<<<(NN * (EMB / 4) + 255) / 256, blk>>>((float4*)x0, NN * (EMB / 4));
    edge_scatter<<<(EE * 32 + 255) / 256, blk>>>(h, ei, x0);
    combine<<<(NN * (EMB / 4) + 255) / 256, blk>>>(x0, h, b_g1, x1);

    // ---- GCN conv 2 ----
    sgemm<false, false, true><<<dim3(3, MB), blk>>>(x1, EMB, W_g2, EMB, nullptr,
                                                    h, EMB, NN, EMB, EMB);
    zero_f4<<<(NN * (EMB / 4) + 255) / 256, blk>>>((float4*)x0, NN * (EMB / 4));
    edge_scatter<<<(EE * 32 + 255) / 256, blk>>>(h, ei, x0);
    combine<<<(NN * (EMB / 4) + 255) / 256, blk>>>(x0, h, b_g2, x1);

    // x4 = leaky(x @ W_o1 + b_o1)
    sgemm<true, true, false><<<dim3(3, MB), blk>>>(x1, EMB, W_o1, EMB, b_o1,
                                                   h, EMB, NN, EMB, EMB);

    // out = x4 @ W_o2 + b_o2
    final_proj<<<(NN * 32 + 255) / 256, blk>>>(h, W_o2, b_o2, out);
}

// round 6
// speedup vs baseline: 1.0034x; 1.0034x over previous
#include <cuda_runtime.h>
#include <cuda_bf16.h>
#include <stdint.h>

#define NN   50000
#define EE   800000
#define EMB  384
#define DESK 768

// ---------------- scratch (no allocations allowed) ----------------
__device__ __align__(16) float g_h  [NN * EMB];
__device__ __align__(16) float g_agg[NN * EMB];
__device__ float g_dinv[NN];
__device__ int   g_deg[NN];
__device__ int   g_is64;

__device__ __align__(16) __nv_bfloat16 g_desh[NN * DESK];
__device__ __align__(16) __nv_bfloat16 g_desl[NN * DESK];
__device__ __align__(16) __nv_bfloat16 g_x0h[NN * EMB];
__device__ __align__(16) __nv_bfloat16 g_x0l[NN * EMB];
__device__ __align__(16) __nv_bfloat16 g_x1h[NN * EMB];
__device__ __align__(16) __nv_bfloat16 g_x1l[NN * EMB];

#define WTOT 688128
__device__ __align__(16) __nv_bfloat16 g_wh[WTOT];
__device__ __align__(16) __nv_bfloat16 g_wl[WTOT];
enum { WOFF_DES = 0, WOFF_IN = 98304, WOFF_G1 = 245760, WOFF_G2 = 393216, WOFF_O1 = 540672 };

__device__ __forceinline__ float leaky(float v) { return v > 0.0f ? v : 0.01f * v; }

__device__ __forceinline__ void split1(float v, __nv_bfloat16& h, __nv_bfloat16& l) {
    h = __float2bfloat16(v);
    l = __float2bfloat16(v - __bfloat162float(h));
}
__device__ __forceinline__ uint32_t packb(__nv_bfloat16 a, __nv_bfloat16 b) {
    __nv_bfloat162 t = __halves2bfloat162(a, b);
    return *(uint32_t*)&t;
}

// ---------------- low-level helpers ----------------
__device__ __forceinline__ uint32_t smem_u32(const void* p) {
    uint32_t a;
    asm("{ .reg .u64 t; cvta.to.shared.u64 t, %1; cvt.u32.u64 %0, t; }" : "=r"(a) : "l"(p));
    return a;
}
__device__ __forceinline__ void cp_async16(uint32_t dst, const void* src) {
    asm volatile("cp.async.cg.shared.global [%0], [%1], 16;" :: "r"(dst), "l"(src));
}
__device__ __forceinline__ void cp_commit() { asm volatile("cp.async.commit_group;" ::: "memory"); }
__device__ __forceinline__ void cp_wait_all() { asm volatile("cp.async.wait_group 0;" ::: "memory"); }
__device__ __forceinline__ void cp_wait_1()  { asm volatile("cp.async.wait_group 1;" ::: "memory"); }

// m16n8k16 bf16 MMA, fp32 accumulate (baseline PTX, sm_80+; HMMA on sm_103)
__device__ __forceinline__ void mma16816(float& d0, float& d1, float& d2, float& d3,
                                         uint32_t a0, uint32_t a1, uint32_t a2, uint32_t a3,
                                         uint32_t b0, uint32_t b1)
{
    asm volatile(
        "mma.sync.aligned.m16n8k16.row.col.f32.bf16.bf16.f32 "
        "{%0,%1,%2,%3}, {%4,%5,%6,%7}, {%8,%9}, {%0,%1,%2,%3};"
        : "+f"(d0), "+f"(d1), "+f"(d2), "+f"(d3)
        : "r"(a0), "r"(a1), "r"(a2), "r"(a3), "r"(b0), "r"(b1));
}

// ---------------- bf16-split HMMA GEMM ----------------
// C tile 128x128 = (Ah+Al)[128,K] x (Bh+Bl)[N,K]^T ; A row-major [M,K], B row-major [N,K].
// SMEM: 2 stages x {Ah, Al, Bh, Bl}, each 128 rows x 32 bf16, row pitch 80B (16B aligned).
#define ROW_PITCH 80
#define TILE_B    (128 * ROW_PITCH)      // 10240
#define STAGE_B   (4 * TILE_B)           // 40960
#define GEMM_SMEM (2 * STAGE_B)          // 81920

template<bool LEAKY_F, bool BIAS_F, bool SCALE_F, bool WF32, bool WSPLIT>
__global__ __launch_bounds__(256) void gemm_hmma(
    const __nv_bfloat16* __restrict__ Ah, const __nv_bfloat16* __restrict__ Al, int K,
    const __nv_bfloat16* __restrict__ Bh, const __nv_bfloat16* __restrict__ Bl,
    const float* __restrict__ bias,
    float* __restrict__ Cf, __nv_bfloat16* __restrict__ Ch, __nv_bfloat16* __restrict__ Cl,
    int ldc, int M)
{
    extern __shared__ char smem[];
    const uint32_t sb = smem_u32(smem);
    const int tid  = threadIdx.x;
    const int wid  = tid >> 5;
    const int lane = tid & 31;
    const int g    = lane >> 2;     // group 0..7
    const int tig  = lane & 3;      // 0..3
    const int warp_m = wid >> 2;    // 0..1
    const int warp_n = wid & 3;     // 0..3
    const int block_row = blockIdx.y * 128;
    const int block_col = blockIdx.x * 128;

    const __nv_bfloat16* bases[4] = { Ah, Al, Bh, Bl };

    float acc[4][4][4];
#pragma unroll
    for (int mt = 0; mt < 4; mt++)
#pragma unroll
        for (int nt = 0; nt < 4; nt++)
#pragma unroll
            for (int q = 0; q < 4; q++) acc[mt][nt][q] = 0.0f;

    const int NC = K >> 5;   // chunks of 32

    // stage loader: 2048 16B granules / 256 threads = 8 each
    auto load_stage = [&](int c, int s) {
        const uint32_t stage = sb + s * STAGE_B;
        const int kbyte = c * 64;   // 32 elems * 2B
#pragma unroll
        for (int i = 0; i < 8; i++) {
            int gi   = tid + i * 256;
            int tile = gi >> 9;            // 0..3
            int r    = (gi >> 2) & 127;
            int c16  = gi & 3;
            int grow;
            if (tile < 2) { grow = block_row + r; if (grow >= M) grow = M - 1; }
            else          { grow = block_col + r; }
            const char* src = (const char*)bases[tile] + (size_t)grow * K * 2 + kbyte + c16 * 16;
            cp_async16(stage + tile * TILE_B + r * ROW_PITCH + c16 * 16, src);
        }
        cp_commit();
    };

    load_stage(0, 0);

    for (int c = 0; c < NC; c++) {
        if (c + 1 < NC) { load_stage(c + 1, (c + 1) & 1); cp_wait_1(); }
        else            { cp_wait_all(); }
        __syncthreads();

        const uint32_t stage = sb + (c & 1) * STAGE_B;
        const uint32_t a_rowbase = stage + (warp_m * 64) * ROW_PITCH;
        const uint32_t b_rowbase = stage + 2 * TILE_B + (warp_n * 32) * ROW_PITCH;

#pragma unroll
        for (int kk = 0; kk < 32; kk += 16) {
            const uint32_t ko = (kk + 2 * tig) * 2;   // bytes
            // A fragments (hi, lo): [arr][mt][4]
            uint32_t af[2][4][4];
#pragma unroll
            for (int arr = 0; arr < 2; arr++) {
                const uint32_t ab = a_rowbase + arr * TILE_B;
#pragma unroll
                for (int mt = 0; mt < 4; mt++) {
                    uint32_t r0 = ab + (mt * 16 + g) * ROW_PITCH + ko;
                    uint32_t r1 = r0 + 8 * ROW_PITCH;
                    asm volatile("ld.shared.b32 %0, [%1];" : "=r"(af[arr][mt][0]) : "r"(r0));
                    asm volatile("ld.shared.b32 %0, [%1];" : "=r"(af[arr][mt][1]) : "r"(r1));
                    asm volatile("ld.shared.b32 %0, [%1];" : "=r"(af[arr][mt][2]) : "r"(r0 + 16));
                    asm volatile("ld.shared.b32 %0, [%1];" : "=r"(af[arr][mt][3]) : "r"(r1 + 16));
                }
            }
            // B fragments (hi, lo): [arr][nt][2]
            uint32_t bf[2][4][2];
#pragma unroll
            for (int arr = 0; arr < 2; arr++) {
                const uint32_t bb = b_rowbase + arr * TILE_B;
#pragma unroll
                for (int nt = 0; nt < 4; nt++) {
                    uint32_t r0 = bb + (nt * 8 + g) * ROW_PITCH + ko;
                    asm volatile("ld.shared.b32 %0, [%1];" : "=r"(bf[arr][nt][0]) : "r"(r0));
                    asm volatile("ld.shared.b32 %0, [%1];" : "=r"(bf[arr][nt][1]) : "r"(r0 + 16));
                }
            }
#pragma unroll
            for (int mt = 0; mt < 4; mt++)
#pragma unroll
                for (int nt = 0; nt < 4; nt++) {
                    float* d = acc[mt][nt];
                    mma16816(d[0], d[1], d[2], d[3],
                             af[0][mt][0], af[0][mt][1], af[0][mt][2], af[0][mt][3],
                             bf[0][nt][0], bf[0][nt][1]);                    // Ah*Bh
                    mma16816(d[0], d[1], d[2], d[3],
                             af[0][mt][0], af[0][mt][1], af[0][mt][2], af[0][mt][3],
                             bf[1][nt][0], bf[1][nt][1]);                    // Ah*Bl
                    mma16816(d[0], d[1], d[2], d[3],
                             af[1][mt][0], af[1][mt][1], af[1][mt][2], af[1][mt][3],
                             bf[0][nt][0], bf[0][nt][1]);                    // Al*Bh
                }
        }
        __syncthreads();
    }

    // ---------------- fused epilogue from register fragments ----------------
#pragma unroll
    for (int mt = 0; mt < 4; mt++) {
#pragma unroll
        for (int nt = 0; nt < 4; nt++) {
            int row0 = block_row + warp_m * 64 + mt * 16 + g;
            int row1 = row0 + 8;
            int col  = block_col + warp_n * 32 + nt * 8 + 2 * tig;
            float b0 = 0.f, b1 = 0.f;
            if (BIAS_F) { b0 = bias[col]; b1 = bias[col + 1]; }
#pragma unroll
            for (int half = 0; half < 2; half++) {
                int row = half ? row1 : row0;
                if (row < M) {
                    float v0 = acc[mt][nt][half * 2 + 0];
                    float v1 = acc[mt][nt][half * 2 + 1];
                    if (BIAS_F)  { v0 += b0; v1 += b1; }
                    if (LEAKY_F) { v0 = leaky(v0); v1 = leaky(v1); }
                    if (SCALE_F) { float dv = g_dinv[row]; v0 *= dv; v1 *= dv; }
                    size_t off = (size_t)row * ldc + col;
                    if (WF32) *(float2*)(Cf + off) = make_float2(v0, v1);
                    if (WSPLIT) {
                        __nv_bfloat16 h0, h1, l0, l1;
                        split1(v0, h0, l0); split1(v1, h1, l1);
                        *(uint32_t*)(Ch + off) = packb(h0, h1);
                        *(uint32_t*)(Cl + off) = packb(l0, l1);
                    }
                }
            }
        }
    }
}

// ---------------- conversions ----------------
__global__ void split_f32(const float* __restrict__ x,
                          __nv_bfloat16* __restrict__ h, __nv_bfloat16* __restrict__ l, int n4)
{
    int i = blockIdx.x * blockDim.x + threadIdx.x;
    if (i >= n4) return;
    float4 v = ((const float4*)x)[i];
    __nv_bfloat16 h0, h1, h2, h3, l0, l1, l2, l3;
    split1(v.x, h0, l0); split1(v.y, h1, l1); split1(v.z, h2, l2); split1(v.w, h3, l3);
    uint2 uh; uh.x = packb(h0, h1); uh.y = packb(h2, h3);
    uint2 ul; ul.x = packb(l0, l1); ul.y = packb(l2, l3);
    ((uint2*)h)[i] = uh;
    ((uint2*)l)[i] = ul;
}

// W [K, Nn] fp32 -> out [Nn, K] bf16 hi/lo (transpose + split)
__global__ void wsplitT(const float* __restrict__ W, int K, int Nn,
                        __nv_bfloat16* __restrict__ oh, __nv_bfloat16* __restrict__ ol)
{
    int idx = blockIdx.x * blockDim.x + threadIdx.x;
    if (idx >= K * Nn) return;
    int k = idx / Nn, n = idx % Nn;
    __nv_bfloat16 h, l; split1(W[idx], h, l);
    oh[(size_t)n * K + k] = h;
    ol[(size_t)n * K + k] = l;
}

// ---------------- small front projections ----------------
__global__ void front_small(const float* __restrict__ nump, const float* __restrict__ catp,
                            const float* __restrict__ Wn, const float* __restrict__ bn,
                            const float* __restrict__ Wc, const float* __restrict__ bc)
{
    int node = blockIdx.x;
    int j = threadIdx.x;   // 0..127
    float n0 = nump[node * 4 + 0], n1 = nump[node * 4 + 1];
    float n2 = nump[node * 4 + 2], n3 = nump[node * 4 + 3];
    float c0 = catp[node * 3 + 0], c1 = catp[node * 3 + 1], c2 = catp[node * 3 + 2];

    float a = bn[j];
    a = fmaf(n0, Wn[0 * 128 + j], a); a = fmaf(n1, Wn[1 * 128 + j], a);
    a = fmaf(n2, Wn[2 * 128 + j], a); a = fmaf(n3, Wn[3 * 128 + j], a);
    float b = bc[j];
    b = fmaf(c0, Wc[0 * 128 + j], b); b = fmaf(c1, Wc[1 * 128 + j], b);
    b = fmaf(c2, Wc[2 * 128 + j], b);

    a = leaky(a); b = leaky(b);
    __nv_bfloat16 h, l;
    size_t base = (size_t)node * EMB;
    split1(a, h, l); g_x0h[base + 128 + j] = h; g_x0l[base + 128 + j] = l;
    split1(b, h, l); g_x0h[base + 256 + j] = h; g_x0l[base + 256 + j] = l;
}

// ---------------- edges ----------------
__device__ __forceinline__ void load_edge(const void* ei, int e, int& src, int& dst) {
    if (g_is64) {
        const long long* p = (const long long*)ei;
        src = (int)p[e]; dst = (int)p[EE + e];
    } else {
        const int* p = (const int*)ei;
        src = p[e]; dst = p[EE + e];
    }
}
__global__ void detect_idx_dtype(const void* ei) {
    const long long* p = (const long long*)ei;
    int ok64 = 1;
    for (int i = 0; i < 64; i++) {
        long long v = p[i];
        if (v < 0 || v >= NN) { ok64 = 0; break; }
    }
    g_is64 = ok64;
}
__global__ void zero_deg() {
    int i = blockIdx.x * blockDim.x + threadIdx.x;
    if (i < NN) g_deg[i] = 0;
}
__global__ void deg_count(const void* __restrict__ ei) {
    int e = blockIdx.x * blockDim.x + threadIdx.x;
    if (e < EE) { int s, d; load_edge(ei, e, s, d); atomicAdd(&g_deg[d], 1); }
}
__global__ void make_dinv() {
    int i = blockIdx.x * blockDim.x + threadIdx.x;
    if (i < NN) g_dinv[i] = rsqrtf((float)g_deg[i] + 1.0f);
}
__global__ void zero_f4(float4* __restrict__ p, int n4) {
    int i = blockIdx.x * blockDim.x + threadIdx.x;
    if (i < n4) p[i] = make_float4(0.f, 0.f, 0.f, 0.f);
}
__global__ __launch_bounds__(256) void edge_scatter(
    const float* __restrict__ y, const void* __restrict__ ei, float* __restrict__ agg)
{
    int warp = (blockIdx.x * blockDim.x + threadIdx.x) >> 5;
    int lane = threadIdx.x & 31;
    if (warp >= EE) return;
    int src, dst; load_edge(ei, warp, src, dst);
    const float4* ys = (const float4*)(y + (size_t)src * EMB);
    float* ad = agg + (size_t)dst * EMB;
#pragma unroll
    for (int i = 0; i < 3; i++) {
        float4 v = ys[lane + i * 32];
        float* p = ad + (size_t)(lane + i * 32) * 4;
        asm volatile("red.global.add.v4.f32 [%0], {%1,%2,%3,%4};"
                     :: "l"(p), "f"(v.x), "f"(v.y), "f"(v.z), "f"(v.w) : "memory");
    }
}

// combine: v = dinv*(agg + y) + b, write bf16 split (feeds next GEMM)
__global__ void combine_split(const float* __restrict__ agg, const float* __restrict__ y,
                              const float* __restrict__ bias,
                              __nv_bfloat16* __restrict__ oh, __nv_bfloat16* __restrict__ ol)
{
    int i = blockIdx.x * blockDim.x + threadIdx.x;   // float4 index
    if (i >= NN * (EMB / 4)) return;
    int row = i / (EMB / 4), colv = i % (EMB / 4);
    float dv = g_dinv[row];
    float4 a = ((const float4*)agg)[i];
    float4 w = ((const float4*)y)[i];
    float4 b = ((const float4*)bias)[colv];
    float v0 = fmaf(dv, a.x + w.x, b.x);
    float v1 = fmaf(dv, a.y + w.y, b.y);
    float v2 = fmaf(dv, a.z + w.z, b.z);
    float v3 = fmaf(dv, a.w + w.w, b.w);
    __nv_bfloat16 h0, h1, h2, h3, l0, l1, l2, l3;
    split1(v0, h0, l0); split1(v1, h1, l1); split1(v2, h2, l2); split1(v3, h3, l3);
    uint2 uh; uh.x = packb(h0, h1); uh.y = packb(h2, h3);
    uint2 ul; ul.x = packb(l0, l1); ul.y = packb(l2, l3);
    ((uint2*)oh)[i] = uh;
    ((uint2*)ol)[i] = ul;
}

// ---------------- final projection ----------------
__global__ __launch_bounds__(256) void final_proj(
    const float* __restrict__ x, const float* __restrict__ W,
    const float* __restrict__ b, float* __restrict__ out)
{
    int warp = (blockIdx.x * blockDim.x + threadIdx.x) >> 5;
    int lane = threadIdx.x & 31;
    if (warp >= NN) return;
    float a0 = 0.f, a1 = 0.f;
    const float* xr = x + (size_t)warp * EMB;
#pragma unroll
    for (int t = 0; t < 12; t++) {
        int k = lane + t * 32;
        float v = xr[k];
        a0 = fmaf(v, W[k * 2 + 0], a0);
        a1 = fmaf(v, W[k * 2 + 1], a1);
    }
#pragma unroll
    for (int off = 16; off > 0; off >>= 1) {
        a0 += __shfl_down_sync(0xffffffffu, a0, off);
        a1 += __shfl_down_sync(0xffffffffu, a1, off);
    }
    if (lane == 0) {
        out[warp * 2 + 0] = a0 + b[0];
        out[warp * 2 + 1] = a1 + b[1];
    }
}

// ---------------- host orchestration ----------------
extern "C" void kernel_launch(void* const* d_in, const int* in_sizes, int n_in,
                              void* d_out, int out_size)
{
    const float* des  = (const float*)d_in[0];
    const float* nump = (const float*)d_in[2];
    const float* catp = (const float*)d_in[3];
    const void*  ei   = d_in[4];
    const float* W_des = (const float*)d_in[5];  const float* b_des = (const float*)d_in[6];
    const float* W_num = (const float*)d_in[7];  const float* b_num = (const float*)d_in[8];
    const float* W_cat = (const float*)d_in[9];  const float* b_cat = (const float*)d_in[10];
    const float* W_in  = (const float*)d_in[11]; const float* b_in  = (const float*)d_in[12];
    const float* W_g1  = (const float*)d_in[13]; const float* b_g1  = (const float*)d_in[14];
    const float* W_g2  = (const float*)d_in[15]; const float* b_g2  = (const float*)d_in[16];
    const float* W_o1  = (const float*)d_in[17]; const float* b_o1  = (const float*)d_in[18];
    const float* W_o2  = (const float*)d_in[19]; const float* b_o2  = (const float*)d_in[20];
    float* out = (float*)d_out;

    float *h, *agg;
    __nv_bfloat16 *desh, *desl, *x0h, *x0l, *x1h, *x1l, *wh, *wl;
    cudaGetSymbolAddress((void**)&h,    g_h);
    cudaGetSymbolAddress((void**)&agg,  g_agg);
    cudaGetSymbolAddress((void**)&desh, g_desh);
    cudaGetSymbolAddress((void**)&desl, g_desl);
    cudaGetSymbolAddress((void**)&x0h,  g_x0h);
    cudaGetSymbolAddress((void**)&x0l,  g_x0l);
    cudaGetSymbolAddress((void**)&x1h,  g_x1h);
    cudaGetSymbolAddress((void**)&x1l,  g_x1l);
    cudaGetSymbolAddress((void**)&wh,   g_wh);
    cudaGetSymbolAddress((void**)&wl,   g_wl);

    cudaFuncSetAttribute(gemm_hmma<true, true, false, false, true>,
                         cudaFuncAttributeMaxDynamicSharedMemorySize, GEMM_SMEM);
    cudaFuncSetAttribute(gemm_hmma<false, false, true, true, false>,
                         cudaFuncAttributeMaxDynamicSharedMemorySize, GEMM_SMEM);
    cudaFuncSetAttribute(gemm_hmma<true, true, false, true, false>,
                         cudaFuncAttributeMaxDynamicSharedMemorySize, GEMM_SMEM);

    const int MB = (NN + 127) / 128;   // 391
    dim3 blk(256);

    detect_idx_dtype<<<1, 1>>>(ei);
    zero_deg<<<(NN + 255) / 256, blk>>>();
    deg_count<<<(EE + 255) / 256, blk>>>(ei);
    make_dinv<<<(NN + 255) / 256, blk>>>();

    // conversions
    split_f32<<<(NN * DESK / 4 + 255) / 256, blk>>>(des, desh, desl, NN * DESK / 4);
    wsplitT<<<(DESK * 128 + 255) / 256, blk>>>(W_des, DESK, 128, wh + WOFF_DES, wl + WOFF_DES);
    wsplitT<<<(EMB * EMB + 255) / 256, blk>>>(W_in, EMB, EMB, wh + WOFF_IN, wl + WOFF_IN);
    wsplitT<<<(EMB * EMB + 255) / 256, blk>>>(W_g1, EMB, EMB, wh + WOFF_G1, wl + WOFF_G1);
    wsplitT<<<(EMB * EMB + 255) / 256, blk>>>(W_g2, EMB, EMB, wh + WOFF_G2, wl + WOFF_G2);
    wsplitT<<<(EMB * EMB + 255) / 256, blk>>>(W_o1, EMB, EMB, wh + WOFF_O1, wl + WOFF_O1);

    // des projection -> x0[:, 0:128] (leaky+bias, split output)
    gemm_hmma<true, true, false, false, true><<<dim3(1, MB), blk, GEMM_SMEM>>>(
        desh, desl, DESK, wh + WOFF_DES, wl + WOFF_DES, b_des,
        nullptr, x0h, x0l, EMB, NN);
    front_small<<<NN, 128>>>(nump, catp, W_num, b_num, W_cat, b_cat);

    // x1 = leaky(x0 @ W_in + b_in)
    gemm_hmma<true, true, false, false, true><<<dim3(3, MB), blk, GEMM_SMEM>>>(
        x0h, x0l, EMB, wh + WOFF_IN, wl + WOFF_IN, b_in,
        nullptr, x1h, x1l, EMB, NN);

    // ---- GCN conv 1 ----
    gemm_hmma<false, false, true, true, false><<<dim3(3, MB), blk, GEMM_SMEM>>>(
        x1h, x1l, EMB, wh + WOFF_G1, wl + WOFF_G1, nullptr,
        h, nullptr, nullptr, EMB, NN);                       // y = (xW)*dinv
    zero_f4<<<(NN * (EMB / 4) + 255) / 256, blk>>>((float4*)agg, NN * (EMB / 4));
    edge_scatter<<<(EE * 32 + 255) / 256, blk>>>(h, ei, agg);
    combine_split<<<(NN * (EMB / 4) + 255) / 256, blk>>>(agg, h, b_g1, x1h, x1l);

    // ---- GCN conv 2 ----
    gemm_hmma<false, false, true, true, false><<<dim3(3, MB), blk, GEMM_SMEM>>>(
        x1h, x1l, EMB, wh + WOFF_G2, wl + WOFF_G2, nullptr,
        h, nullptr, nullptr, EMB, NN);
    zero_f4<<<(NN * (EMB / 4) + 255) / 256, blk>>>((float4*)agg, NN * (EMB / 4));
    edge_scatter<<<(EE * 32 + 255) / 256, blk>>>(h, ei, agg);
    combine_split<<<(NN * (EMB / 4) + 255) / 256, blk>>>(agg, h, b_g2, x1h, x1l);

    // x4 = leaky(x @ W_o1 + b_o1)
    gemm_hmma<true, true, false, true, false><<<dim3(3, MB), blk, GEMM_SMEM>>>(
        x1h, x1l, EMB, wh + WOFF_O1, wl + WOFF_O1, b_o1,
        h, nullptr, nullptr, EMB, NN);

    // out = x4 @ W_o2 + b_o2
    final_proj<<<(NN * 32 + 255) / 256, blk>>>(h, W_o2, b_o2, out);
}

// round 7
// speedup vs baseline: 1.8043x; 1.7982x over previous
#include <cuda_runtime.h>
#include <cuda_bf16.h>
#include <stdint.h>

#define NN   50000
#define EE   800000
#define EMB  384
#define DESK 768

// ---------------- scratch (no allocations allowed) ----------------
__device__ __align__(16) float g_h  [NN * EMB];
__device__ float g_dinv[NN];
__device__ int   g_deg[NN];
__device__ int   g_rowptr[NN + 1];
__device__ int   g_cursor[NN];
__device__ int   g_csr[EE];
__device__ int   g_is64;

__device__ __align__(16) __nv_bfloat16 g_desh[NN * DESK];
__device__ __align__(16) __nv_bfloat16 g_desl[NN * DESK];
__device__ __align__(16) __nv_bfloat16 g_x0h[NN * EMB];
__device__ __align__(16) __nv_bfloat16 g_x0l[NN * EMB];
__device__ __align__(16) __nv_bfloat16 g_x1h[NN * EMB];
__device__ __align__(16) __nv_bfloat16 g_x1l[NN * EMB];

#define WTOT 688128
__device__ __align__(16) __nv_bfloat16 g_wh[WTOT];
__device__ __align__(16) __nv_bfloat16 g_wl[WTOT];
enum { WOFF_DES = 0, WOFF_IN = 98304, WOFF_G1 = 245760, WOFF_G2 = 393216, WOFF_O1 = 540672 };

__device__ __forceinline__ float leaky(float v) { return v > 0.0f ? v : 0.01f * v; }

__device__ __forceinline__ void split1(float v, __nv_bfloat16& h, __nv_bfloat16& l) {
    h = __float2bfloat16(v);
    l = __float2bfloat16(v - __bfloat162float(h));
}
__device__ __forceinline__ uint32_t packb(__nv_bfloat16 a, __nv_bfloat16 b) {
    __nv_bfloat162 t = __halves2bfloat162(a, b);
    return *(uint32_t*)&t;
}

// ---------------- low-level helpers ----------------
__device__ __forceinline__ uint32_t smem_u32(const void* p) {
    uint32_t a;
    asm("{ .reg .u64 t; cvta.to.shared.u64 t, %1; cvt.u32.u64 %0, t; }" : "=r"(a) : "l"(p));
    return a;
}
__device__ __forceinline__ void cp_async16(uint32_t dst, const void* src) {
    asm volatile("cp.async.cg.shared.global [%0], [%1], 16;" :: "r"(dst), "l"(src));
}
__device__ __forceinline__ void cp_commit() { asm volatile("cp.async.commit_group;" ::: "memory"); }
__device__ __forceinline__ void cp_wait_all() { asm volatile("cp.async.wait_group 0;" ::: "memory"); }
__device__ __forceinline__ void cp_wait_1()  { asm volatile("cp.async.wait_group 1;" ::: "memory"); }

// m16n8k16 bf16 MMA, fp32 accumulate
__device__ __forceinline__ void mma16816(float& d0, float& d1, float& d2, float& d3,
                                         uint32_t a0, uint32_t a1, uint32_t a2, uint32_t a3,
                                         uint32_t b0, uint32_t b1)
{
    asm volatile(
        "mma.sync.aligned.m16n8k16.row.col.f32.bf16.bf16.f32 "
        "{%0,%1,%2,%3}, {%4,%5,%6,%7}, {%8,%9}, {%0,%1,%2,%3};"
        : "+f"(d0), "+f"(d1), "+f"(d2), "+f"(d3)
        : "r"(a0), "r"(a1), "r"(a2), "r"(a3), "r"(b0), "r"(b1));
}

// ---------------- bf16-split HMMA GEMM (unchanged from validated R5) ----------------
#define ROW_PITCH 80
#define TILE_B    (128 * ROW_PITCH)
#define STAGE_B   (4 * TILE_B)
#define GEMM_SMEM (2 * STAGE_B)

template<bool LEAKY_F, bool BIAS_F, bool SCALE_F, bool WF32, bool WSPLIT>
__global__ __launch_bounds__(256) void gemm_hmma(
    const __nv_bfloat16* __restrict__ Ah, const __nv_bfloat16* __restrict__ Al, int K,
    const __nv_bfloat16* __restrict__ Bh, const __nv_bfloat16* __restrict__ Bl,
    const float* __restrict__ bias,
    float* __restrict__ Cf, __nv_bfloat16* __restrict__ Ch, __nv_bfloat16* __restrict__ Cl,
    int ldc, int M)
{
    extern __shared__ char smem[];
    const uint32_t sb = smem_u32(smem);
    const int tid  = threadIdx.x;
    const int wid  = tid >> 5;
    const int lane = tid & 31;
    const int g    = lane >> 2;
    const int tig  = lane & 3;
    const int warp_m = wid >> 2;
    const int warp_n = wid & 3;
    const int block_row = blockIdx.y * 128;
    const int block_col = blockIdx.x * 128;

    const __nv_bfloat16* bases[4] = { Ah, Al, Bh, Bl };

    float acc[4][4][4];
#pragma unroll
    for (int mt = 0; mt < 4; mt++)
#pragma unroll
        for (int nt = 0; nt < 4; nt++)
#pragma unroll
            for (int q = 0; q < 4; q++) acc[mt][nt][q] = 0.0f;

    const int NC = K >> 5;

    auto load_stage = [&](int c, int s) {
        const uint32_t stage = sb + s * STAGE_B;
        const int kbyte = c * 64;
#pragma unroll
        for (int i = 0; i < 8; i++) {
            int gi   = tid + i * 256;
            int tile = gi >> 9;
            int r    = (gi >> 2) & 127;
            int c16  = gi & 3;
            int grow;
            if (tile < 2) { grow = block_row + r; if (grow >= M) grow = M - 1; }
            else          { grow = block_col + r; }
            const char* src = (const char*)bases[tile] + (size_t)grow * K * 2 + kbyte + c16 * 16;
            cp_async16(stage + tile * TILE_B + r * ROW_PITCH + c16 * 16, src);
        }
        cp_commit();
    };

    load_stage(0, 0);

    for (int c = 0; c < NC; c++) {
        if (c + 1 < NC) { load_stage(c + 1, (c + 1) & 1); cp_wait_1(); }
        else            { cp_wait_all(); }
        __syncthreads();

        const uint32_t stage = sb + (c & 1) * STAGE_B;
        const uint32_t a_rowbase = stage + (warp_m * 64) * ROW_PITCH;
        const uint32_t b_rowbase = stage + 2 * TILE_B + (warp_n * 32) * ROW_PITCH;

#pragma unroll
        for (int kk = 0; kk < 32; kk += 16) {
            const uint32_t ko = (kk + 2 * tig) * 2;
            uint32_t af[2][4][4];
#pragma unroll
            for (int arr = 0; arr < 2; arr++) {
                const uint32_t ab = a_rowbase + arr * TILE_B;
#pragma unroll
                for (int mt = 0; mt < 4; mt++) {
                    uint32_t r0 = ab + (mt * 16 + g) * ROW_PITCH + ko;
                    uint32_t r1 = r0 + 8 * ROW_PITCH;
                    asm volatile("ld.shared.b32 %0, [%1];" : "=r"(af[arr][mt][0]) : "r"(r0));
                    asm volatile("ld.shared.b32 %0, [%1];" : "=r"(af[arr][mt][1]) : "r"(r1));
                    asm volatile("ld.shared.b32 %0, [%1];" : "=r"(af[arr][mt][2]) : "r"(r0 + 16));
                    asm volatile("ld.shared.b32 %0, [%1];" : "=r"(af[arr][mt][3]) : "r"(r1 + 16));
                }
            }
            uint32_t bf[2][4][2];
#pragma unroll
            for (int arr = 0; arr < 2; arr++) {
                const uint32_t bb = b_rowbase + arr * TILE_B;
#pragma unroll
                for (int nt = 0; nt < 4; nt++) {
                    uint32_t r0 = bb + (nt * 8 + g) * ROW_PITCH + ko;
                    asm volatile("ld.shared.b32 %0, [%1];" : "=r"(bf[arr][nt][0]) : "r"(r0));
                    asm volatile("ld.shared.b32 %0, [%1];" : "=r"(bf[arr][nt][1]) : "r"(r0 + 16));
                }
            }
#pragma unroll
            for (int mt = 0; mt < 4; mt++)
#pragma unroll
                for (int nt = 0; nt < 4; nt++) {
                    float* d = acc[mt][nt];
                    mma16816(d[0], d[1], d[2], d[3],
                             af[0][mt][0], af[0][mt][1], af[0][mt][2], af[0][mt][3],
                             bf[0][nt][0], bf[0][nt][1]);
                    mma16816(d[0], d[1], d[2], d[3],
                             af[0][mt][0], af[0][mt][1], af[0][mt][2], af[0][mt][3],
                             bf[1][nt][0], bf[1][nt][1]);
                    mma16816(d[0], d[1], d[2], d[3],
                             af[1][mt][0], af[1][mt][1], af[1][mt][2], af[1][mt][3],
                             bf[0][nt][0], bf[0][nt][1]);
                }
        }
        __syncthreads();
    }

#pragma unroll
    for (int mt = 0; mt < 4; mt++) {
#pragma unroll
        for (int nt = 0; nt < 4; nt++) {
            int row0 = block_row + warp_m * 64 + mt * 16 + g;
            int row1 = row0 + 8;
            int col  = block_col + warp_n * 32 + nt * 8 + 2 * tig;
            float b0 = 0.f, b1 = 0.f;
            if (BIAS_F) { b0 = bias[col]; b1 = bias[col + 1]; }
#pragma unroll
            for (int half = 0; half < 2; half++) {
                int row = half ? row1 : row0;
                if (row < M) {
                    float v0 = acc[mt][nt][half * 2 + 0];
                    float v1 = acc[mt][nt][half * 2 + 1];
                    if (BIAS_F)  { v0 += b0; v1 += b1; }
                    if (LEAKY_F) { v0 = leaky(v0); v1 = leaky(v1); }
                    if (SCALE_F) { float dv = g_dinv[row]; v0 *= dv; v1 *= dv; }
                    size_t off = (size_t)row * ldc + col;
                    if (WF32) *(float2*)(Cf + off) = make_float2(v0, v1);
                    if (WSPLIT) {
                        __nv_bfloat16 h0, h1, l0, l1;
                        split1(v0, h0, l0); split1(v1, h1, l1);
                        *(uint32_t*)(Ch + off) = packb(h0, h1);
                        *(uint32_t*)(Cl + off) = packb(l0, l1);
                    }
                }
            }
        }
    }
}

// ---------------- conversions ----------------
__global__ void split_f32(const float* __restrict__ x,
                          __nv_bfloat16* __restrict__ h, __nv_bfloat16* __restrict__ l, int n4)
{
    int i = blockIdx.x * blockDim.x + threadIdx.x;
    if (i >= n4) return;
    float4 v = ((const float4*)x)[i];
    __nv_bfloat16 h0, h1, h2, h3, l0, l1, l2, l3;
    split1(v.x, h0, l0); split1(v.y, h1, l1); split1(v.z, h2, l2); split1(v.w, h3, l3);
    uint2 uh; uh.x = packb(h0, h1); uh.y = packb(h2, h3);
    uint2 ul; ul.x = packb(l0, l1); ul.y = packb(l2, l3);
    ((uint2*)h)[i] = uh;
    ((uint2*)l)[i] = ul;
}

__global__ void wsplitT(const float* __restrict__ W, int K, int Nn,
                        __nv_bfloat16* __restrict__ oh, __nv_bfloat16* __restrict__ ol)
{
    int idx = blockIdx.x * blockDim.x + threadIdx.x;
    if (idx >= K * Nn) return;
    int k = idx / Nn, n = idx % Nn;
    __nv_bfloat16 h, l; split1(W[idx], h, l);
    oh[(size_t)n * K + k] = h;
    ol[(size_t)n * K + k] = l;
}

// ---------------- small front projections ----------------
__global__ void front_small(const float* __restrict__ nump, const float* __restrict__ catp,
                            const float* __restrict__ Wn, const float* __restrict__ bn,
                            const float* __restrict__ Wc, const float* __restrict__ bc)
{
    int node = blockIdx.x;
    int j = threadIdx.x;
    float n0 = nump[node * 4 + 0], n1 = nump[node * 4 + 1];
    float n2 = nump[node * 4 + 2], n3 = nump[node * 4 + 3];
    float c0 = catp[node * 3 + 0], c1 = catp[node * 3 + 1], c2 = catp[node * 3 + 2];

    float a = bn[j];
    a = fmaf(n0, Wn[0 * 128 + j], a); a = fmaf(n1, Wn[1 * 128 + j], a);
    a = fmaf(n2, Wn[2 * 128 + j], a); a = fmaf(n3, Wn[3 * 128 + j], a);
    float b = bc[j];
    b = fmaf(c0, Wc[0 * 128 + j], b); b = fmaf(c1, Wc[1 * 128 + j], b);
    b = fmaf(c2, Wc[2 * 128 + j], b);

    a = leaky(a); b = leaky(b);
    __nv_bfloat16 h, l;
    size_t base = (size_t)node * EMB;
    split1(a, h, l); g_x0h[base + 128 + j] = h; g_x0l[base + 128 + j] = l;
    split1(b, h, l); g_x0h[base + 256 + j] = h; g_x0l[base + 256 + j] = l;
}

// ---------------- edges / CSR ----------------
__device__ __forceinline__ void load_edge(const void* ei, int e, int& src, int& dst) {
    if (g_is64) {
        const long long* p = (const long long*)ei;
        src = (int)p[e]; dst = (int)p[EE + e];
    } else {
        const int* p = (const int*)ei;
        src = p[e]; dst = p[EE + e];
    }
}
__global__ void detect_idx_dtype(const void* ei) {
    const long long* p = (const long long*)ei;
    int ok64 = 1;
    for (int i = 0; i < 64; i++) {
        long long v = p[i];
        if (v < 0 || v >= NN) { ok64 = 0; break; }
    }
    g_is64 = ok64;
}
__global__ void zero_deg() {
    int i = blockIdx.x * blockDim.x + threadIdx.x;
    if (i < NN) g_deg[i] = 0;
}
__global__ void deg_count(const void* __restrict__ ei) {
    int e = blockIdx.x * blockDim.x + threadIdx.x;
    if (e < EE) { int s, d; load_edge(ei, e, s, d); atomicAdd(&g_deg[d], 1); }
}

// single-block scan over degrees -> rowptr, cursor, dinv
#define SCAN_T 1024
#define SEG ((NN + SCAN_T - 1) / SCAN_T)   // 49
__global__ __launch_bounds__(SCAN_T) void scan_rowptr() {
    __shared__ int part[SCAN_T];
    int t = threadIdx.x;
    int s0 = t * SEG, s1 = min(s0 + SEG, NN);
    int sum = 0;
    for (int i = s0; i < s1; i++) sum += g_deg[i];
    part[t] = sum;
    __syncthreads();
    for (int off = 1; off < SCAN_T; off <<= 1) {
        int v = (t >= off) ? part[t - off] : 0;
        __syncthreads();
        part[t] += v;
        __syncthreads();
    }
    int run = (t == 0) ? 0 : part[t - 1];
    for (int i = s0; i < s1; i++) {
        g_rowptr[i] = run;
        g_cursor[i] = run;
        int d = g_deg[i];
        g_dinv[i] = rsqrtf((float)d + 1.0f);
        run += d;
    }
    if (s1 == NN && s0 < NN) g_rowptr[NN] = run;
}

__global__ void csr_fill(const void* __restrict__ ei) {
    int e = blockIdx.x * blockDim.x + threadIdx.x;
    if (e < EE) {
        int s, d; load_edge(ei, e, s, d);
        int pos = atomicAdd(&g_cursor[d], 1);
        g_csr[pos] = s;
    }
}

// ---------------- fused gather-aggregate + combine + split ----------------
// one warp per dst node: out = dinv[n]*(sum_{src} y[src] + y[n]) + bias, split to bf16 hi/lo
__global__ __launch_bounds__(256) void gcn_agg(
    const float* __restrict__ y, const float* __restrict__ bias,
    __nv_bfloat16* __restrict__ oh, __nv_bfloat16* __restrict__ ol)
{
    int warp = (blockIdx.x * blockDim.x + threadIdx.x) >> 5;
    int lane = threadIdx.x & 31;
    if (warp >= NN) return;
    int beg = g_rowptr[warp], end = g_rowptr[warp + 1];

    float4 a0 = make_float4(0.f, 0.f, 0.f, 0.f);
    float4 a1 = a0, a2 = a0;

    for (int base = beg; base < end; base += 32) {
        int cnt = min(32, end - base);
        int s = (lane < cnt) ? g_csr[base + lane] : 0;
        for (int j = 0; j < cnt; j++) {
            int sj = __shfl_sync(0xffffffffu, s, j);
            const float4* ys = (const float4*)(y + (size_t)sj * EMB);
            float4 v0 = ys[lane], v1 = ys[lane + 32], v2 = ys[lane + 64];
            a0.x += v0.x; a0.y += v0.y; a0.z += v0.z; a0.w += v0.w;
            a1.x += v1.x; a1.y += v1.y; a1.z += v1.z; a1.w += v1.w;
            a2.x += v2.x; a2.y += v2.y; a2.z += v2.z; a2.w += v2.w;
        }
    }
    // self term
    const float4* yn = (const float4*)(y + (size_t)warp * EMB);
    float4 s0 = yn[lane], s1 = yn[lane + 32], s2 = yn[lane + 64];
    a0.x += s0.x; a0.y += s0.y; a0.z += s0.z; a0.w += s0.w;
    a1.x += s1.x; a1.y += s1.y; a1.z += s1.z; a1.w += s1.w;
    a2.x += s2.x; a2.y += s2.y; a2.z += s2.z; a2.w += s2.w;

    float dv = g_dinv[warp];
    const float4* bv = (const float4*)bias;
    float4 b0 = bv[lane], b1 = bv[lane + 32], b2 = bv[lane + 64];

    float r[12];
    r[0] = fmaf(dv, a0.x, b0.x); r[1] = fmaf(dv, a0.y, b0.y);
    r[2] = fmaf(dv, a0.z, b0.z); r[3] = fmaf(dv, a0.w, b0.w);
    r[4] = fmaf(dv, a1.x, b1.x); r[5] = fmaf(dv, a1.y, b1.y);
    r[6] = fmaf(dv, a1.z, b1.z); r[7] = fmaf(dv, a1.w, b1.w);
    r[8] = fmaf(dv, a2.x, b2.x); r[9] = fmaf(dv, a2.y, b2.y);
    r[10] = fmaf(dv, a2.z, b2.z); r[11] = fmaf(dv, a2.w, b2.w);

    uint2* ohp = (uint2*)(oh + (size_t)warp * EMB);
    uint2* olp = (uint2*)(ol + (size_t)warp * EMB);
#pragma unroll
    for (int q = 0; q < 3; q++) {
        __nv_bfloat16 h0, h1, h2, h3, l0, l1, l2, l3;
        split1(r[q * 4 + 0], h0, l0); split1(r[q * 4 + 1], h1, l1);
        split1(r[q * 4 + 2], h2, l2); split1(r[q * 4 + 3], h3, l3);
        uint2 uh; uh.x = packb(h0, h1); uh.y = packb(h2, h3);
        uint2 ul; ul.x = packb(l0, l1); ul.y = packb(l2, l3);
        ohp[lane + q * 32] = uh;
        olp[lane + q * 32] = ul;
    }
}

// ---------------- final projection ----------------
__global__ __launch_bounds__(256) void final_proj(
    const float* __restrict__ x, const float* __restrict__ W,
    const float* __restrict__ b, float* __restrict__ out)
{
    int warp = (blockIdx.x * blockDim.x + threadIdx.x) >> 5;
    int lane = threadIdx.x & 31;
    if (warp >= NN) return;
    float a0 = 0.f, a1 = 0.f;
    const float* xr = x + (size_t)warp * EMB;
#pragma unroll
    for (int t = 0; t < 12; t++) {
        int k = lane + t * 32;
        float v = xr[k];
        a0 = fmaf(v, W[k * 2 + 0], a0);
        a1 = fmaf(v, W[k * 2 + 1], a1);
    }
#pragma unroll
    for (int off = 16; off > 0; off >>= 1) {
        a0 += __shfl_down_sync(0xffffffffu, a0, off);
        a1 += __shfl_down_sync(0xffffffffu, a1, off);
    }
    if (lane == 0) {
        out[warp * 2 + 0] = a0 + b[0];
        out[warp * 2 + 1] = a1 + b[1];
    }
}

// ---------------- host orchestration ----------------
extern "C" void kernel_launch(void* const* d_in, const int* in_sizes, int n_in,
                              void* d_out, int out_size)
{
    const float* des  = (const float*)d_in[0];
    const float* nump = (const float*)d_in[2];
    const float* catp = (const float*)d_in[3];
    const void*  ei   = d_in[4];
    const float* W_des = (const float*)d_in[5];  const float* b_des = (const float*)d_in[6];
    const float* W_num = (const float*)d_in[7];  const float* b_num = (const float*)d_in[8];
    const float* W_cat = (const float*)d_in[9];  const float* b_cat = (const float*)d_in[10];
    const float* W_in  = (const float*)d_in[11]; const float* b_in  = (const float*)d_in[12];
    const float* W_g1  = (const float*)d_in[13]; const float* b_g1  = (const float*)d_in[14];
    const float* W_g2  = (const float*)d_in[15]; const float* b_g2  = (const float*)d_in[16];
    const float* W_o1  = (const float*)d_in[17]; const float* b_o1  = (const float*)d_in[18];
    const float* W_o2  = (const float*)d_in[19]; const float* b_o2  = (const float*)d_in[20];
    float* out = (float*)d_out;

    float *h;
    __nv_bfloat16 *desh, *desl, *x0h, *x0l, *x1h, *x1l, *wh, *wl;
    cudaGetSymbolAddress((void**)&h,    g_h);
    cudaGetSymbolAddress((void**)&desh, g_desh);
    cudaGetSymbolAddress((void**)&desl, g_desl);
    cudaGetSymbolAddress((void**)&x0h,  g_x0h);
    cudaGetSymbolAddress((void**)&x0l,  g_x0l);
    cudaGetSymbolAddress((void**)&x1h,  g_x1h);
    cudaGetSymbolAddress((void**)&x1l,  g_x1l);
    cudaGetSymbolAddress((void**)&wh,   g_wh);
    cudaGetSymbolAddress((void**)&wl,   g_wl);

    cudaFuncSetAttribute(gemm_hmma<true, true, false, false, true>,
                         cudaFuncAttributeMaxDynamicSharedMemorySize, GEMM_SMEM);
    cudaFuncSetAttribute(gemm_hmma<false, false, true, true, false>,
                         cudaFuncAttributeMaxDynamicSharedMemorySize, GEMM_SMEM);
    cudaFuncSetAttribute(gemm_hmma<true, true, false, true, false>,
                         cudaFuncAttributeMaxDynamicSharedMemorySize, GEMM_SMEM);

    const int MB = (NN + 127) / 128;   // 391
    dim3 blk(256);

    // edge preprocessing: dtype probe -> degree -> scan(rowptr,cursor,dinv) -> CSR fill
    detect_idx_dtype<<<1, 1>>>(ei);
    zero_deg<<<(NN + 255) / 256, blk>>>();
    deg_count<<<(EE + 255) / 256, blk>>>(ei);
    scan_rowptr<<<1, SCAN_T>>>();
    csr_fill<<<(EE + 255) / 256, blk>>>(ei);

    // conversions
    split_f32<<<(NN * DESK / 4 + 255) / 256, blk>>>(des, desh, desl, NN * DESK / 4);
    wsplitT<<<(DESK * 128 + 255) / 256, blk>>>(W_des, DESK, 128, wh + WOFF_DES, wl + WOFF_DES);
    wsplitT<<<(EMB * EMB + 255) / 256, blk>>>(W_in, EMB, EMB, wh + WOFF_IN, wl + WOFF_IN);
    wsplitT<<<(EMB * EMB + 255) / 256, blk>>>(W_g1, EMB, EMB, wh + WOFF_G1, wl + WOFF_G1);
    wsplitT<<<(EMB * EMB + 255) / 256, blk>>>(W_g2, EMB, EMB, wh + WOFF_G2, wl + WOFF_G2);
    wsplitT<<<(EMB * EMB + 255) / 256, blk>>>(W_o1, EMB, EMB, wh + WOFF_O1, wl + WOFF_O1);

    // des projection -> x0[:, 0:128]
    gemm_hmma<true, true, false, false, true><<<dim3(1, MB), blk, GEMM_SMEM>>>(
        desh, desl, DESK, wh + WOFF_DES, wl + WOFF_DES, b_des,
        nullptr, x0h, x0l, EMB, NN);
    front_small<<<NN, 128>>>(nump, catp, W_num, b_num, W_cat, b_cat);

    // x1 = leaky(x0 @ W_in + b_in)
    gemm_hmma<true, true, false, false, true><<<dim3(3, MB), blk, GEMM_SMEM>>>(
        x0h, x0l, EMB, wh + WOFF_IN, wl + WOFF_IN, b_in,
        nullptr, x1h, x1l, EMB, NN);

    // ---- GCN conv 1 ----  y = (x1 W)*dinv ; x1' = agg(y) (fused combine+split)
    gemm_hmma<false, false, true, true, false><<<dim3(3, MB), blk, GEMM_SMEM>>>(
        x1h, x1l, EMB, wh + WOFF_G1, wl + WOFF_G1, nullptr,
        h, nullptr, nullptr, EMB, NN);
    gcn_agg<<<(NN * 32 + 255) / 256, blk>>>(h, b_g1, x1h, x1l);

    // ---- GCN conv 2 ----
    gemm_hmma<false, false, true, true, false><<<dim3(3, MB), blk, GEMM_SMEM>>>(
        x1h, x1l, EMB, wh + WOFF_G2, wl + WOFF_G2, nullptr,
        h, nullptr, nullptr, EMB, NN);
    gcn_agg<<<(NN * 32 + 255) / 256, blk>>>(h, b_g2, x1h, x1l);

    // x4 = leaky(x @ W_o1 + b_o1)
    gemm_hmma<true, true, false, true, false><<<dim3(3, MB), blk, GEMM_SMEM>>>(
        x1h, x1l, EMB, wh + WOFF_O1, wl + WOFF_O1, b_o1,
        h, nullptr, nullptr, EMB, NN);

    // out = x4 @ W_o2 + b_o2
    final_proj<<<(NN * 32 + 255) / 256, blk>>>(h, W_o2, b_o2, out);
}

// round 8
// speedup vs baseline: 2.0237x; 1.1216x over previous
#include <cuda_runtime.h>
#include <cuda_bf16.h>
#include <stdint.h>

#define NN   50000
#define EE   800000
#define EMB  384
#define DESK 768

// ---------------- scratch (no allocations allowed) ----------------
__device__ __align__(16) float g_h  [NN * EMB];
__device__ float g_dinv[NN];
__device__ int   g_deg[NN];
__device__ int   g_rowptr[NN + 1];
__device__ int   g_cursor[NN];
__device__ int   g_csr[EE];
__device__ int   g_scan[NN];
__device__ int   g_bsum[256];
__device__ int   g_boff[256];
__device__ int   g_is64;

__device__ __align__(16) __nv_bfloat16 g_desh[NN * DESK];
__device__ __align__(16) __nv_bfloat16 g_desl[NN * DESK];
__device__ __align__(16) __nv_bfloat16 g_x0h[NN * EMB];
__device__ __align__(16) __nv_bfloat16 g_x0l[NN * EMB];
__device__ __align__(16) __nv_bfloat16 g_x1h[NN * EMB];
__device__ __align__(16) __nv_bfloat16 g_x1l[NN * EMB];

#define WTOT 688128
__device__ __align__(16) __nv_bfloat16 g_wh[WTOT];
__device__ __align__(16) __nv_bfloat16 g_wl[WTOT];
enum { WOFF_DES = 0, WOFF_IN = 98304, WOFF_G1 = 245760, WOFF_G2 = 393216, WOFF_O1 = 540672 };

__device__ __forceinline__ float leaky(float v) { return v > 0.0f ? v : 0.01f * v; }

__device__ __forceinline__ void split1(float v, __nv_bfloat16& h, __nv_bfloat16& l) {
    h = __float2bfloat16(v);
    l = __float2bfloat16(v - __bfloat162float(h));
}
__device__ __forceinline__ uint32_t packb(__nv_bfloat16 a, __nv_bfloat16 b) {
    __nv_bfloat162 t = __halves2bfloat162(a, b);
    return *(uint32_t*)&t;
}

// ---------------- low-level helpers ----------------
__device__ __forceinline__ uint32_t smem_u32(const void* p) {
    uint32_t a;
    asm("{ .reg .u64 t; cvta.to.shared.u64 t, %1; cvt.u32.u64 %0, t; }" : "=r"(a) : "l"(p));
    return a;
}
__device__ __forceinline__ void cp_async16(uint32_t dst, const void* src) {
    asm volatile("cp.async.cg.shared.global [%0], [%1], 16;" :: "r"(dst), "l"(src));
}
__device__ __forceinline__ void cp_commit() { asm volatile("cp.async.commit_group;" ::: "memory"); }
__device__ __forceinline__ void cp_wait_all() { asm volatile("cp.async.wait_group 0;" ::: "memory"); }
__device__ __forceinline__ void cp_wait_1()  { asm volatile("cp.async.wait_group 1;" ::: "memory"); }

__device__ __forceinline__ void mma16816(float& d0, float& d1, float& d2, float& d3,
                                         uint32_t a0, uint32_t a1, uint32_t a2, uint32_t a3,
                                         uint32_t b0, uint32_t b1)
{
    asm volatile(
        "mma.sync.aligned.m16n8k16.row.col.f32.bf16.bf16.f32 "
        "{%0,%1,%2,%3}, {%4,%5,%6,%7}, {%8,%9}, {%0,%1,%2,%3};"
        : "+f"(d0), "+f"(d1), "+f"(d2), "+f"(d3)
        : "r"(a0), "r"(a1), "r"(a2), "r"(a3), "r"(b0), "r"(b1));
}
__device__ __forceinline__ void ldsm4(uint32_t& r0, uint32_t& r1, uint32_t& r2, uint32_t& r3,
                                      uint32_t addr)
{
    asm volatile("ldmatrix.sync.aligned.m8n8.x4.shared.b16 {%0,%1,%2,%3}, [%4];"
                 : "=r"(r0), "=r"(r1), "=r"(r2), "=r"(r3) : "r"(addr));
}

// ---------------- bf16-split HMMA GEMM ----------------
#define ROW_PITCH 80
#define TILE_B    (128 * ROW_PITCH)
#define STAGE_B   (4 * TILE_B)
#define GEMM_SMEM (2 * STAGE_B)

template<bool LEAKY_F, bool BIAS_F, bool SCALE_F, bool WF32, bool WSPLIT, bool FUSE>
__global__ __launch_bounds__(256) void gemm_hmma(
    const __nv_bfloat16* __restrict__ Ah, const __nv_bfloat16* __restrict__ Al, int K,
    const __nv_bfloat16* __restrict__ Bh, const __nv_bfloat16* __restrict__ Bl,
    const float* __restrict__ bias,
    float* __restrict__ Cf, __nv_bfloat16* __restrict__ Ch, __nv_bfloat16* __restrict__ Cl,
    int ldc, int M,
    const float* __restrict__ Wo2, float* __restrict__ Out)
{
    extern __shared__ char smem[];
    const uint32_t sb = smem_u32(smem);
    const int tid  = threadIdx.x;
    const int wid  = tid >> 5;
    const int lane = tid & 31;
    const int g    = lane >> 2;
    const int tig  = lane & 3;
    const int warp_m = wid >> 2;
    const int warp_n = wid & 3;
    const int block_row = blockIdx.y * 128;
    const int block_col = blockIdx.x * 128;

    const __nv_bfloat16* bases[4] = { Ah, Al, Bh, Bl };

    float acc[4][4][4];
#pragma unroll
    for (int mt = 0; mt < 4; mt++)
#pragma unroll
        for (int nt = 0; nt < 4; nt++)
#pragma unroll
            for (int q = 0; q < 4; q++) acc[mt][nt][q] = 0.0f;

    const int NC = K >> 5;

    auto load_stage = [&](int c, int s) {
        const uint32_t stage = sb + s * STAGE_B;
        const int kbyte = c * 64;
#pragma unroll
        for (int i = 0; i < 8; i++) {
            int gi   = tid + i * 256;
            int tile = gi >> 9;
            int r    = (gi >> 2) & 127;
            int c16  = gi & 3;
            int grow;
            if (tile < 2) { grow = block_row + r; if (grow >= M) grow = M - 1; }
            else          { grow = block_col + r; }
            const char* src = (const char*)bases[tile] + (size_t)grow * K * 2 + kbyte + c16 * 16;
            cp_async16(stage + tile * TILE_B + r * ROW_PITCH + c16 * 16, src);
        }
        cp_commit();
    };

    // per-thread ldmatrix address offsets (within a stage)
    const uint32_t aOff = (uint32_t)(warp_m * 64 + (lane & 15)) * ROW_PITCH + (lane >> 4) * 16;
    const uint32_t bOff = 2 * TILE_B
                        + (uint32_t)(warp_n * 32 + (lane & 7) + ((lane >> 4) * 8)) * ROW_PITCH
                        + ((lane >> 3) & 1) * 16;

    load_stage(0, 0);

    for (int c = 0; c < NC; c++) {
        if (c + 1 < NC) { load_stage(c + 1, (c + 1) & 1); cp_wait_1(); }
        else            { cp_wait_all(); }
        __syncthreads();

        const uint32_t stage = sb + (c & 1) * STAGE_B;
        const uint32_t aBase = stage + aOff;
        const uint32_t bBase = stage + bOff;

#pragma unroll
        for (int kk = 0; kk < 32; kk += 16) {
            const uint32_t ko = kk * 2;   // uniform byte offset for ldmatrix
            uint32_t af[2][4][4];
#pragma unroll
            for (int arr = 0; arr < 2; arr++)
#pragma unroll
                for (int mt = 0; mt < 4; mt++)
                    ldsm4(af[arr][mt][0], af[arr][mt][1], af[arr][mt][2], af[arr][mt][3],
                          aBase + arr * TILE_B + mt * (16 * ROW_PITCH) + ko);

            uint32_t bf[2][4][2];
#pragma unroll
            for (int arr = 0; arr < 2; arr++)
#pragma unroll
                for (int p = 0; p < 2; p++)
                    ldsm4(bf[arr][2 * p][0], bf[arr][2 * p][1],
                          bf[arr][2 * p + 1][0], bf[arr][2 * p + 1][1],
                          bBase + arr * TILE_B + p * (16 * ROW_PITCH) + ko);

#pragma unroll
            for (int mt = 0; mt < 4; mt++)
#pragma unroll
                for (int nt = 0; nt < 4; nt++) {
                    float* d = acc[mt][nt];
                    mma16816(d[0], d[1], d[2], d[3],
                             af[0][mt][0], af[0][mt][1], af[0][mt][2], af[0][mt][3],
                             bf[0][nt][0], bf[0][nt][1]);
                    mma16816(d[0], d[1], d[2], d[3],
                             af[0][mt][0], af[0][mt][1], af[0][mt][2], af[0][mt][3],
                             bf[1][nt][0], bf[1][nt][1]);
                    mma16816(d[0], d[1], d[2], d[3],
                             af[1][mt][0], af[1][mt][1], af[1][mt][2], af[1][mt][3],
                             bf[0][nt][0], bf[0][nt][1]);
                }
        }
        __syncthreads();
    }

    if (FUSE) {
        // fused: logits += leaky(acc + bias) @ Wo2   (Out pre-initialized with b_o2)
#pragma unroll
        for (int mt = 0; mt < 4; mt++) {
#pragma unroll
            for (int half = 0; half < 2; half++) {
                int row = block_row + warp_m * 64 + mt * 16 + g + half * 8;
                if (row < M) {
                    float s0 = 0.f, s1 = 0.f;
#pragma unroll
                    for (int nt = 0; nt < 4; nt++) {
                        int col = block_col + warp_n * 32 + nt * 8 + 2 * tig;
                        float v0 = acc[mt][nt][half * 2 + 0] + bias[col];
                        float v1 = acc[mt][nt][half * 2 + 1] + bias[col + 1];
                        v0 = leaky(v0); v1 = leaky(v1);
                        s0 += v0 * Wo2[col * 2 + 0] + v1 * Wo2[(col + 1) * 2 + 0];
                        s1 += v0 * Wo2[col * 2 + 1] + v1 * Wo2[(col + 1) * 2 + 1];
                    }
                    s0 += __shfl_xor_sync(0xffffffffu, s0, 1);
                    s0 += __shfl_xor_sync(0xffffffffu, s0, 2);
                    s1 += __shfl_xor_sync(0xffffffffu, s1, 1);
                    s1 += __shfl_xor_sync(0xffffffffu, s1, 2);
                    if (tig == 0) {
                        atomicAdd(&Out[row * 2 + 0], s0);
                        atomicAdd(&Out[row * 2 + 1], s1);
                    }
                }
            }
        }
    } else {
#pragma unroll
        for (int mt = 0; mt < 4; mt++) {
#pragma unroll
            for (int nt = 0; nt < 4; nt++) {
                int row0 = block_row + warp_m * 64 + mt * 16 + g;
                int row1 = row0 + 8;
                int col  = block_col + warp_n * 32 + nt * 8 + 2 * tig;
                float b0 = 0.f, b1 = 0.f;
                if (BIAS_F) { b0 = bias[col]; b1 = bias[col + 1]; }
#pragma unroll
                for (int half = 0; half < 2; half++) {
                    int row = half ? row1 : row0;
                    if (row < M) {
                        float v0 = acc[mt][nt][half * 2 + 0];
                        float v1 = acc[mt][nt][half * 2 + 1];
                        if (BIAS_F)  { v0 += b0; v1 += b1; }
                        if (LEAKY_F) { v0 = leaky(v0); v1 = leaky(v1); }
                        if (SCALE_F) { float dv = g_dinv[row]; v0 *= dv; v1 *= dv; }
                        size_t off = (size_t)row * ldc + col;
                        if (WF32) *(float2*)(Cf + off) = make_float2(v0, v1);
                        if (WSPLIT) {
                            __nv_bfloat16 h0, h1, l0, l1;
                            split1(v0, h0, l0); split1(v1, h1, l1);
                            *(uint32_t*)(Ch + off) = packb(h0, h1);
                            *(uint32_t*)(Cl + off) = packb(l0, l1);
                        }
                    }
                }
            }
        }
    }
}

// ---------------- conversions ----------------
__global__ void split_f32(const float* __restrict__ x,
                          __nv_bfloat16* __restrict__ h, __nv_bfloat16* __restrict__ l, int n4)
{
    int i = blockIdx.x * blockDim.x + threadIdx.x;
    if (i >= n4) return;
    float4 v = ((const float4*)x)[i];
    __nv_bfloat16 h0, h1, h2, h3, l0, l1, l2, l3;
    split1(v.x, h0, l0); split1(v.y, h1, l1); split1(v.z, h2, l2); split1(v.w, h3, l3);
    uint2 uh; uh.x = packb(h0, h1); uh.y = packb(h2, h3);
    uint2 ul; ul.x = packb(l0, l1); ul.y = packb(l2, l3);
    ((uint2*)h)[i] = uh;
    ((uint2*)l)[i] = ul;
}

__global__ void wsplitT(const float* __restrict__ W, int K, int Nn,
                        __nv_bfloat16* __restrict__ oh, __nv_bfloat16* __restrict__ ol)
{
    int idx = blockIdx.x * blockDim.x + threadIdx.x;
    if (idx >= K * Nn) return;
    int k = idx / Nn, n = idx % Nn;
    __nv_bfloat16 h, l; split1(W[idx], h, l);
    oh[(size_t)n * K + k] = h;
    ol[(size_t)n * K + k] = l;
}

// ---------------- small front projections ----------------
__global__ void front_small(const float* __restrict__ nump, const float* __restrict__ catp,
                            const float* __restrict__ Wn, const float* __restrict__ bn,
                            const float* __restrict__ Wc, const float* __restrict__ bc)
{
    int node = blockIdx.x;
    int j = threadIdx.x;
    float n0 = nump[node * 4 + 0], n1 = nump[node * 4 + 1];
    float n2 = nump[node * 4 + 2], n3 = nump[node * 4 + 3];
    float c0 = catp[node * 3 + 0], c1 = catp[node * 3 + 1], c2 = catp[node * 3 + 2];

    float a = bn[j];
    a = fmaf(n0, Wn[0 * 128 + j], a); a = fmaf(n1, Wn[1 * 128 + j], a);
    a = fmaf(n2, Wn[2 * 128 + j], a); a = fmaf(n3, Wn[3 * 128 + j], a);
    float b = bc[j];
    b = fmaf(c0, Wc[0 * 128 + j], b); b = fmaf(c1, Wc[1 * 128 + j], b);
    b = fmaf(c2, Wc[2 * 128 + j], b);

    a = leaky(a); b = leaky(b);
    __nv_bfloat16 h, l;
    size_t base = (size_t)node * EMB;
    split1(a, h, l); g_x0h[base + 128 + j] = h; g_x0l[base + 128 + j] = l;
    split1(b, h, l); g_x0h[base + 256 + j] = h; g_x0l[base + 256 + j] = l;
}

// ---------------- edges / CSR ----------------
__device__ __forceinline__ void load_edge(const void* ei, int e, int& src, int& dst) {
    if (g_is64) {
        const long long* p = (const long long*)ei;
        src = (int)p[e]; dst = (int)p[EE + e];
    } else {
        const int* p = (const int*)ei;
        src = p[e]; dst = p[EE + e];
    }
}
__global__ void detect_idx_dtype(const void* ei) {
    const long long* p = (const long long*)ei;
    int ok64 = 1;
    for (int i = 0; i < 64; i++) {
        long long v = p[i];
        if (v < 0 || v >= NN) { ok64 = 0; break; }
    }
    g_is64 = ok64;
}
__global__ void zero_deg() {
    int i = blockIdx.x * blockDim.x + threadIdx.x;
    if (i < NN) g_deg[i] = 0;
}
__global__ void deg_count(const void* __restrict__ ei) {
    int e = blockIdx.x * blockDim.x + threadIdx.x;
    if (e < EE) { int s, d; load_edge(ei, e, s, d); atomicAdd(&g_deg[d], 1); }
}

// ---- parallel 3-phase scan ----
#define SCAN_BLKS ((NN + 255) / 256)   // 196
__global__ void scan_phase1() {
    __shared__ int ws[8];
    int i = blockIdx.x * 256 + threadIdx.x;
    int lane = threadIdx.x & 31, wd = threadIdx.x >> 5;
    int v = (i < NN) ? g_deg[i] : 0;
    int s = v;
#pragma unroll
    for (int o = 1; o < 32; o <<= 1) {
        int t = __shfl_up_sync(0xffffffffu, s, o);
        if (lane >= o) s += t;
    }
    if (lane == 31) ws[wd] = s;
    __syncthreads();
    if (wd == 0) {
        int u = (lane < 8) ? ws[lane] : 0;
        int ss = u;
#pragma unroll
        for (int o = 1; o < 8; o <<= 1) {
            int t = __shfl_up_sync(0xffffffffu, ss, o);
            if (lane >= o) ss += t;
        }
        if (lane < 8) ws[lane] = ss;
    }
    __syncthreads();
    int incl = s + (wd ? ws[wd - 1] : 0);
    if (i < NN) g_scan[i] = incl;
    if (threadIdx.x == 255) g_bsum[blockIdx.x] = incl;
}
__global__ void scan_phase2() {
    __shared__ int ws[8];
    int t = threadIdx.x;
    int lane = t & 31, wd = t >> 5;
    int v = (t < SCAN_BLKS) ? g_bsum[t] : 0;
    int s = v;
#pragma unroll
    for (int o = 1; o < 32; o <<= 1) {
        int u = __shfl_up_sync(0xffffffffu, s, o);
        if (lane >= o) s += u;
    }
    if (lane == 31) ws[wd] = s;
    __syncthreads();
    if (wd == 0) {
        int u = (lane < 8) ? ws[lane] : 0;
        int ss = u;
#pragma unroll
        for (int o = 1; o < 8; o <<= 1) {
            int x = __shfl_up_sync(0xffffffffu, ss, o);
            if (lane >= o) ss += x;
        }
        if (lane < 8) ws[lane] = ss;
    }
    __syncthreads();
    int incl = s + (wd ? ws[wd - 1] : 0);
    if (t < SCAN_BLKS) g_boff[t] = incl - v;   // exclusive block offset
}
__global__ void scan_phase3() {
    int i = blockIdx.x * 256 + threadIdx.x;
    if (i >= NN) return;
    int incl = g_scan[i] + g_boff[blockIdx.x];
    int d = g_deg[i];
    int beg = incl - d;
    g_rowptr[i] = beg;
    g_cursor[i] = beg;
    g_dinv[i] = rsqrtf((float)d + 1.0f);
    if (i == NN - 1) g_rowptr[NN] = incl;
}

__global__ void csr_fill(const void* __restrict__ ei) {
    int e = blockIdx.x * blockDim.x + threadIdx.x;
    if (e < EE) {
        int s, d; load_edge(ei, e, s, d);
        int pos = atomicAdd(&g_cursor[d], 1);
        g_csr[pos] = s;
    }
}

// ---------------- fused gather-aggregate + combine + split ----------------
__global__ __launch_bounds__(256) void gcn_agg(
    const float* __restrict__ y, const float* __restrict__ bias,
    __nv_bfloat16* __restrict__ oh, __nv_bfloat16* __restrict__ ol)
{
    int warp = (blockIdx.x * blockDim.x + threadIdx.x) >> 5;
    int lane = threadIdx.x & 31;
    if (warp >= NN) return;
    int beg = g_rowptr[warp], end = g_rowptr[warp + 1];

    float4 a0 = make_float4(0.f, 0.f, 0.f, 0.f);
    float4 a1 = a0, a2 = a0;

    for (int base = beg; base < end; base += 32) {
        int cnt = min(32, end - base);
        int s = (lane < cnt) ? g_csr[base + lane] : 0;
        for (int j = 0; j < cnt; j++) {
            int sj = __shfl_sync(0xffffffffu, s, j);
            const float4* ys = (const float4*)(y + (size_t)sj * EMB);
            float4 v0 = ys[lane], v1 = ys[lane + 32], v2 = ys[lane + 64];
            a0.x += v0.x; a0.y += v0.y; a0.z += v0.z; a0.w += v0.w;
            a1.x += v1.x; a1.y += v1.y; a1.z += v1.z; a1.w += v1.w;
            a2.x += v2.x; a2.y += v2.y; a2.z += v2.z; a2.w += v2.w;
        }
    }
    const float4* yn = (const float4*)(y + (size_t)warp * EMB);
    float4 s0 = yn[lane], s1 = yn[lane + 32], s2 = yn[lane + 64];
    a0.x += s0.x; a0.y += s0.y; a0.z += s0.z; a0.w += s0.w;
    a1.x += s1.x; a1.y += s1.y; a1.z += s1.z; a1.w += s1.w;
    a2.x += s2.x; a2.y += s2.y; a2.z += s2.z; a2.w += s2.w;

    float dv = g_dinv[warp];
    const float4* bv = (const float4*)bias;
    float4 b0 = bv[lane], b1 = bv[lane + 32], b2 = bv[lane + 64];

    float r[12];
    r[0] = fmaf(dv, a0.x, b0.x); r[1] = fmaf(dv, a0.y, b0.y);
    r[2] = fmaf(dv, a0.z, b0.z); r[3] = fmaf(dv, a0.w, b0.w);
    r[4] = fmaf(dv, a1.x, b1.x); r[5] = fmaf(dv, a1.y, b1.y);
    r[6] = fmaf(dv, a1.z, b1.z); r[7] = fmaf(dv, a1.w, b1.w);
    r[8] = fmaf(dv, a2.x, b2.x); r[9] = fmaf(dv, a2.y, b2.y);
    r[10] = fmaf(dv, a2.z, b2.z); r[11] = fmaf(dv, a2.w, b2.w);

    uint2* ohp = (uint2*)(oh + (size_t)warp * EMB);
    uint2* olp = (uint2*)(ol + (size_t)warp * EMB);
#pragma unroll
    for (int q = 0; q < 3; q++) {
        __nv_bfloat16 h0, h1, h2, h3, l0, l1, l2, l3;
        split1(r[q * 4 + 0], h0, l0); split1(r[q * 4 + 1], h1, l1);
        split1(r[q * 4 + 2], h2, l2); split1(r[q * 4 + 3], h3, l3);
        uint2 uh; uh.x = packb(h0, h1); uh.y = packb(h2, h3);
        uint2 ul; ul.x = packb(l0, l1); ul.y = packb(l2, l3);
        ohp[lane + q * 32] = uh;
        olp[lane + q * 32] = ul;
    }
}

// ---------------- output init with bias ----------------
__global__ void init_out(float* __restrict__ out, const float* __restrict__ b) {
    int i = blockIdx.x * blockDim.x + threadIdx.x;
    if (i < NN) {
        out[i * 2 + 0] = b[0];
        out[i * 2 + 1] = b[1];
    }
}

// ---------------- host orchestration ----------------
extern "C" void kernel_launch(void* const* d_in, const int* in_sizes, int n_in,
                              void* d_out, int out_size)
{
    const float* des  = (const float*)d_in[0];
    const float* nump = (const float*)d_in[2];
    const float* catp = (const float*)d_in[3];
    const void*  ei   = d_in[4];
    const float* W_des = (const float*)d_in[5];  const float* b_des = (const float*)d_in[6];
    const float* W_num = (const float*)d_in[7];  const float* b_num = (const float*)d_in[8];
    const float* W_cat = (const float*)d_in[9];  const float* b_cat = (const float*)d_in[10];
    const float* W_in  = (const float*)d_in[11]; const float* b_in  = (const float*)d_in[12];
    const float* W_g1  = (const float*)d_in[13]; const float* b_g1  = (const float*)d_in[14];
    const float* W_g2  = (const float*)d_in[15]; const float* b_g2  = (const float*)d_in[16];
    const float* W_o1  = (const float*)d_in[17]; const float* b_o1  = (const float*)d_in[18];
    const float* W_o2  = (const float*)d_in[19]; const float* b_o2  = (const float*)d_in[20];
    float* out = (float*)d_out;

    float *h;
    __nv_bfloat16 *desh, *desl, *x0h, *x0l, *x1h, *x1l, *wh, *wl;
    cudaGetSymbolAddress((void**)&h,    g_h);
    cudaGetSymbolAddress((void**)&desh, g_desh);
    cudaGetSymbolAddress((void**)&desl, g_desl);
    cudaGetSymbolAddress((void**)&x0h,  g_x0h);
    cudaGetSymbolAddress((void**)&x0l,  g_x0l);
    cudaGetSymbolAddress((void**)&x1h,  g_x1h);
    cudaGetSymbolAddress((void**)&x1l,  g_x1l);
    cudaGetSymbolAddress((void**)&wh,   g_wh);
    cudaGetSymbolAddress((void**)&wl,   g_wl);

    cudaFuncSetAttribute(gemm_hmma<true, true, false, false, true, false>,
                         cudaFuncAttributeMaxDynamicSharedMemorySize, GEMM_SMEM);
    cudaFuncSetAttribute(gemm_hmma<false, false, true, true, false, false>,
                         cudaFuncAttributeMaxDynamicSharedMemorySize, GEMM_SMEM);
    cudaFuncSetAttribute(gemm_hmma<true, true, false, false, false, true>,
                         cudaFuncAttributeMaxDynamicSharedMemorySize, GEMM_SMEM);

    const int MB = (NN + 127) / 128;   // 391
    dim3 blk(256);

    // edge preprocessing
    detect_idx_dtype<<<1, 1>>>(ei);
    zero_deg<<<(NN + 255) / 256, blk>>>();
    deg_count<<<(EE + 255) / 256, blk>>>(ei);
    scan_phase1<<<SCAN_BLKS, 256>>>();
    scan_phase2<<<1, 256>>>();
    scan_phase3<<<SCAN_BLKS, 256>>>();
    csr_fill<<<(EE + 255) / 256, blk>>>(ei);

    // conversions
    split_f32<<<(NN * DESK / 4 + 255) / 256, blk>>>(des, desh, desl, NN * DESK / 4);
    wsplitT<<<(DESK * 128 + 255) / 256, blk>>>(W_des, DESK, 128, wh + WOFF_DES, wl + WOFF_DES);
    wsplitT<<<(EMB * EMB + 255) / 256, blk>>>(W_in, EMB, EMB, wh + WOFF_IN, wl + WOFF_IN);
    wsplitT<<<(EMB * EMB + 255) / 256, blk>>>(W_g1, EMB, EMB, wh + WOFF_G1, wl + WOFF_G1);
    wsplitT<<<(EMB * EMB + 255) / 256, blk>>>(W_g2, EMB, EMB, wh + WOFF_G2, wl + WOFF_G2);
    wsplitT<<<(EMB * EMB + 255) / 256, blk>>>(W_o1, EMB, EMB, wh + WOFF_O1, wl + WOFF_O1);

    // des projection -> x0[:, 0:128]
    gemm_hmma<true, true, false, false, true, false><<<dim3(1, MB), blk, GEMM_SMEM>>>(
        desh, desl, DESK, wh + WOFF_DES, wl + WOFF_DES, b_des,
        nullptr, x0h, x0l, EMB, NN, nullptr, nullptr);
    front_small<<<NN, 128>>>(nump, catp, W_num, b_num, W_cat, b_cat);

    // x1 = leaky(x0 @ W_in + b_in)
    gemm_hmma<true, true, false, false, true, false><<<dim3(3, MB), blk, GEMM_SMEM>>>(
        x0h, x0l, EMB, wh + WOFF_IN, wl + WOFF_IN, b_in,
        nullptr, x1h, x1l, EMB, NN, nullptr, nullptr);

    // ---- GCN conv 1 ----
    gemm_hmma<false, false, true, true, false, false><<<dim3(3, MB), blk, GEMM_SMEM>>>(
        x1h, x1l, EMB, wh + WOFF_G1, wl + WOFF_G1, nullptr,
        h, nullptr, nullptr, EMB, NN, nullptr, nullptr);
    gcn_agg<<<(NN * 32 + 255) / 256, blk>>>(h, b_g1, x1h, x1l);

    // ---- GCN conv 2 ----
    gemm_hmma<false, false, true, true, false, false><<<dim3(3, MB), blk, GEMM_SMEM>>>(
        x1h, x1l, EMB, wh + WOFF_G2, wl + WOFF_G2, nullptr,
        h, nullptr, nullptr, EMB, NN, nullptr, nullptr);
    gcn_agg<<<(NN * 32 + 255) / 256, blk>>>(h, b_g2, x1h, x1l);

    // fused: out = leaky(x @ W_o1 + b_o1) @ W_o2 + b_o2
    init_out<<<(NN + 255) / 256, blk>>>(out, b_o2);
    gemm_hmma<true, true, false, false, false, true><<<dim3(3, MB), blk, GEMM_SMEM>>>(
        x1h, x1l, EMB, wh + WOFF_O1, wl + WOFF_O1, b_o1,
        nullptr, nullptr, nullptr, EMB, NN, W_o2, out);
}

// round 9
// speedup vs baseline: 2.1378x; 1.0564x over previous
#include <cuda_runtime.h>
#include <cuda_bf16.h>
#include <cuda_fp16.h>
#include <stdint.h>

#define NN   50000
#define EE   800000
#define EMB  384
#define DESK 768

// ---------------- scratch (no allocations allowed) ----------------
__device__ __align__(16) __half g_h[NN * EMB];      // fp16 message rows
__device__ float g_dinv[NN];
__device__ int   g_deg[NN];
__device__ int   g_rowptr[NN + 1];
__device__ int   g_cursor[NN];
__device__ int   g_csr[EE];
__device__ int   g_scan[NN];
__device__ int   g_bsum[256];
__device__ int   g_boff[256];
__device__ int   g_is64;

__device__ __align__(16) __nv_bfloat16 g_desh[NN * DESK];
__device__ __align__(16) __nv_bfloat16 g_desl[NN * DESK];
__device__ __align__(16) __nv_bfloat16 g_x0h[NN * EMB];
__device__ __align__(16) __nv_bfloat16 g_x0l[NN * EMB];
__device__ __align__(16) __nv_bfloat16 g_x1h[NN * EMB];
__device__ __align__(16) __nv_bfloat16 g_x1l[NN * EMB];

#define WTOT 688128
__device__ __align__(16) __nv_bfloat16 g_wh[WTOT];
__device__ __align__(16) __nv_bfloat16 g_wl[WTOT];
enum { WOFF_DES = 0, WOFF_IN = 98304, WOFF_G1 = 245760, WOFF_G2 = 393216, WOFF_O1 = 540672 };

__device__ __forceinline__ float leaky(float v) { return v > 0.0f ? v : 0.01f * v; }

__device__ __forceinline__ void split1(float v, __nv_bfloat16& h, __nv_bfloat16& l) {
    h = __float2bfloat16(v);
    l = __float2bfloat16(v - __bfloat162float(h));
}
__device__ __forceinline__ uint32_t packb(__nv_bfloat16 a, __nv_bfloat16 b) {
    __nv_bfloat162 t = __halves2bfloat162(a, b);
    return *(uint32_t*)&t;
}

// ---------------- low-level helpers ----------------
__device__ __forceinline__ uint32_t smem_u32(const void* p) {
    uint32_t a;
    asm("{ .reg .u64 t; cvta.to.shared.u64 t, %1; cvt.u32.u64 %0, t; }" : "=r"(a) : "l"(p));
    return a;
}
__device__ __forceinline__ void cp_async16(uint32_t dst, const void* src) {
    asm volatile("cp.async.cg.shared.global [%0], [%1], 16;" :: "r"(dst), "l"(src));
}
__device__ __forceinline__ void cp_commit() { asm volatile("cp.async.commit_group;" ::: "memory"); }
__device__ __forceinline__ void cp_wait_all() { asm volatile("cp.async.wait_group 0;" ::: "memory"); }
__device__ __forceinline__ void cp_wait_1()  { asm volatile("cp.async.wait_group 1;" ::: "memory"); }

__device__ __forceinline__ void mma16816(float& d0, float& d1, float& d2, float& d3,
                                         uint32_t a0, uint32_t a1, uint32_t a2, uint32_t a3,
                                         uint32_t b0, uint32_t b1)
{
    asm volatile(
        "mma.sync.aligned.m16n8k16.row.col.f32.bf16.bf16.f32 "
        "{%0,%1,%2,%3}, {%4,%5,%6,%7}, {%8,%9}, {%0,%1,%2,%3};"
        : "+f"(d0), "+f"(d1), "+f"(d2), "+f"(d3)
        : "r"(a0), "r"(a1), "r"(a2), "r"(a3), "r"(b0), "r"(b1));
}
__device__ __forceinline__ void ldsm4(uint32_t& r0, uint32_t& r1, uint32_t& r2, uint32_t& r3,
                                      uint32_t addr)
{
    asm volatile("ldmatrix.sync.aligned.m8n8.x4.shared.b16 {%0,%1,%2,%3}, [%4];"
                 : "=r"(r0), "=r"(r1), "=r"(r2), "=r"(r3) : "r"(addr));
}

// ---------------- bf16-split HMMA GEMM ----------------
#define ROW_PITCH 80
#define TILE_B    (128 * ROW_PITCH)
#define STAGE_B   (4 * TILE_B)
#define GEMM_SMEM (2 * STAGE_B)

template<bool LEAKY_F, bool BIAS_F, bool SCALE_F, bool WHALF, bool WSPLIT, bool FUSE>
__global__ __launch_bounds__(256) void gemm_hmma(
    const __nv_bfloat16* __restrict__ Ah, const __nv_bfloat16* __restrict__ Al, int K,
    const __nv_bfloat16* __restrict__ Bh, const __nv_bfloat16* __restrict__ Bl,
    const float* __restrict__ bias,
    __half* __restrict__ Cf, __nv_bfloat16* __restrict__ Ch, __nv_bfloat16* __restrict__ Cl,
    int ldc, int M,
    const float* __restrict__ Wo2, float* __restrict__ Out)
{
    extern __shared__ char smem[];
    const uint32_t sb = smem_u32(smem);
    const int tid  = threadIdx.x;
    const int wid  = tid >> 5;
    const int lane = tid & 31;
    const int g    = lane >> 2;
    const int tig  = lane & 3;
    const int warp_m = wid >> 2;
    const int warp_n = wid & 3;
    const int block_row = blockIdx.y * 128;
    const int block_col = blockIdx.x * 128;

    const __nv_bfloat16* bases[4] = { Ah, Al, Bh, Bl };

    float acc[4][4][4];
#pragma unroll
    for (int mt = 0; mt < 4; mt++)
#pragma unroll
        for (int nt = 0; nt < 4; nt++)
#pragma unroll
            for (int q = 0; q < 4; q++) acc[mt][nt][q] = 0.0f;

    const int NC = K >> 5;

    auto load_stage = [&](int c, int s) {
        const uint32_t stage = sb + s * STAGE_B;
        const int kbyte = c * 64;
#pragma unroll
        for (int i = 0; i < 8; i++) {
            int gi   = tid + i * 256;
            int tile = gi >> 9;
            int r    = (gi >> 2) & 127;
            int c16  = gi & 3;
            int grow;
            if (tile < 2) { grow = block_row + r; if (grow >= M) grow = M - 1; }
            else          { grow = block_col + r; }
            const char* src = (const char*)bases[tile] + (size_t)grow * K * 2 + kbyte + c16 * 16;
            cp_async16(stage + tile * TILE_B + r * ROW_PITCH + c16 * 16, src);
        }
        cp_commit();
    };

    const uint32_t aOff = (uint32_t)(warp_m * 64 + (lane & 15)) * ROW_PITCH + (lane >> 4) * 16;
    const uint32_t bOff = 2 * TILE_B
                        + (uint32_t)(warp_n * 32 + (lane & 7) + ((lane >> 4) * 8)) * ROW_PITCH
                        + ((lane >> 3) & 1) * 16;

    load_stage(0, 0);

    for (int c = 0; c < NC; c++) {
        if (c + 1 < NC) { load_stage(c + 1, (c + 1) & 1); cp_wait_1(); }
        else            { cp_wait_all(); }
        __syncthreads();

        const uint32_t stage = sb + (c & 1) * STAGE_B;
        const uint32_t aBase = stage + aOff;
        const uint32_t bBase = stage + bOff;

#pragma unroll
        for (int kk = 0; kk < 32; kk += 16) {
            const uint32_t ko = kk * 2;
            uint32_t af[2][4][4];
#pragma unroll
            for (int arr = 0; arr < 2; arr++)
#pragma unroll
                for (int mt = 0; mt < 4; mt++)
                    ldsm4(af[arr][mt][0], af[arr][mt][1], af[arr][mt][2], af[arr][mt][3],
                          aBase + arr * TILE_B + mt * (16 * ROW_PITCH) + ko);

            uint32_t bf[2][4][2];
#pragma unroll
            for (int arr = 0; arr < 2; arr++)
#pragma unroll
                for (int p = 0; p < 2; p++)
                    ldsm4(bf[arr][2 * p][0], bf[arr][2 * p][1],
                          bf[arr][2 * p + 1][0], bf[arr][2 * p + 1][1],
                          bBase + arr * TILE_B + p * (16 * ROW_PITCH) + ko);

#pragma unroll
            for (int mt = 0; mt < 4; mt++)
#pragma unroll
                for (int nt = 0; nt < 4; nt++) {
                    float* d = acc[mt][nt];
                    mma16816(d[0], d[1], d[2], d[3],
                             af[0][mt][0], af[0][mt][1], af[0][mt][2], af[0][mt][3],
                             bf[0][nt][0], bf[0][nt][1]);
                    mma16816(d[0], d[1], d[2], d[3],
                             af[0][mt][0], af[0][mt][1], af[0][mt][2], af[0][mt][3],
                             bf[1][nt][0], bf[1][nt][1]);
                    mma16816(d[0], d[1], d[2], d[3],
                             af[1][mt][0], af[1][mt][1], af[1][mt][2], af[1][mt][3],
                             bf[0][nt][0], bf[0][nt][1]);
                }
        }
        __syncthreads();
    }

    if (FUSE) {
#pragma unroll
        for (int mt = 0; mt < 4; mt++) {
#pragma unroll
            for (int half = 0; half < 2; half++) {
                int row = block_row + warp_m * 64 + mt * 16 + g + half * 8;
                if (row < M) {
                    float s0 = 0.f, s1 = 0.f;
#pragma unroll
                    for (int nt = 0; nt < 4; nt++) {
                        int col = block_col + warp_n * 32 + nt * 8 + 2 * tig;
                        float v0 = acc[mt][nt][half * 2 + 0] + bias[col];
                        float v1 = acc[mt][nt][half * 2 + 1] + bias[col + 1];
                        v0 = leaky(v0); v1 = leaky(v1);
                        s0 += v0 * Wo2[col * 2 + 0] + v1 * Wo2[(col + 1) * 2 + 0];
                        s1 += v0 * Wo2[col * 2 + 1] + v1 * Wo2[(col + 1) * 2 + 1];
                    }
                    s0 += __shfl_xor_sync(0xffffffffu, s0, 1);
                    s0 += __shfl_xor_sync(0xffffffffu, s0, 2);
                    s1 += __shfl_xor_sync(0xffffffffu, s1, 1);
                    s1 += __shfl_xor_sync(0xffffffffu, s1, 2);
                    if (tig == 0) {
                        atomicAdd(&Out[row * 2 + 0], s0);
                        atomicAdd(&Out[row * 2 + 1], s1);
                    }
                }
            }
        }
    } else {
#pragma unroll
        for (int mt = 0; mt < 4; mt++) {
#pragma unroll
            for (int nt = 0; nt < 4; nt++) {
                int row0 = block_row + warp_m * 64 + mt * 16 + g;
                int row1 = row0 + 8;
                int col  = block_col + warp_n * 32 + nt * 8 + 2 * tig;
                float b0 = 0.f, b1 = 0.f;
                if (BIAS_F) { b0 = bias[col]; b1 = bias[col + 1]; }
#pragma unroll
                for (int half = 0; half < 2; half++) {
                    int row = half ? row1 : row0;
                    if (row < M) {
                        float v0 = acc[mt][nt][half * 2 + 0];
                        float v1 = acc[mt][nt][half * 2 + 1];
                        if (BIAS_F)  { v0 += b0; v1 += b1; }
                        if (LEAKY_F) { v0 = leaky(v0); v1 = leaky(v1); }
                        if (SCALE_F) { float dv = g_dinv[row]; v0 *= dv; v1 *= dv; }
                        size_t off = (size_t)row * ldc + col;
                        if (WHALF) *(__half2*)(Cf + off) = __floats2half2_rn(v0, v1);
                        if (WSPLIT) {
                            __nv_bfloat16 h0, h1, l0, l1;
                            split1(v0, h0, l0); split1(v1, h1, l1);
                            *(uint32_t*)(Ch + off) = packb(h0, h1);
                            *(uint32_t*)(Cl + off) = packb(l0, l1);
                        }
                    }
                }
            }
        }
    }
}

// ---------------- conversions ----------------
__global__ void split_f32(const float* __restrict__ x,
                          __nv_bfloat16* __restrict__ h, __nv_bfloat16* __restrict__ l, int n4)
{
    int i = blockIdx.x * blockDim.x + threadIdx.x;
    if (i >= n4) return;
    float4 v = ((const float4*)x)[i];
    __nv_bfloat16 h0, h1, h2, h3, l0, l1, l2, l3;
    split1(v.x, h0, l0); split1(v.y, h1, l1); split1(v.z, h2, l2); split1(v.w, h3, l3);
    uint2 uh; uh.x = packb(h0, h1); uh.y = packb(h2, h3);
    uint2 ul; ul.x = packb(l0, l1); ul.y = packb(l2, l3);
    ((uint2*)h)[i] = uh;
    ((uint2*)l)[i] = ul;
}

__global__ void wsplitT(const float* __restrict__ W, int K, int Nn,
                        __nv_bfloat16* __restrict__ oh, __nv_bfloat16* __restrict__ ol)
{
    int idx = blockIdx.x * blockDim.x + threadIdx.x;
    if (idx >= K * Nn) return;
    int k = idx / Nn, n = idx % Nn;
    __nv_bfloat16 h, l; split1(W[idx], h, l);
    oh[(size_t)n * K + k] = h;
    ol[(size_t)n * K + k] = l;
}

// ---------------- small front projections ----------------
__global__ void front_small(const float* __restrict__ nump, const float* __restrict__ catp,
                            const float* __restrict__ Wn, const float* __restrict__ bn,
                            const float* __restrict__ Wc, const float* __restrict__ bc)
{
    int node = blockIdx.x;
    int j = threadIdx.x;
    float n0 = nump[node * 4 + 0], n1 = nump[node * 4 + 1];
    float n2 = nump[node * 4 + 2], n3 = nump[node * 4 + 3];
    float c0 = catp[node * 3 + 0], c1 = catp[node * 3 + 1], c2 = catp[node * 3 + 2];

    float a = bn[j];
    a = fmaf(n0, Wn[0 * 128 + j], a); a = fmaf(n1, Wn[1 * 128 + j], a);
    a = fmaf(n2, Wn[2 * 128 + j], a); a = fmaf(n3, Wn[3 * 128 + j], a);
    float b = bc[j];
    b = fmaf(c0, Wc[0 * 128 + j], b); b = fmaf(c1, Wc[1 * 128 + j], b);
    b = fmaf(c2, Wc[2 * 128 + j], b);

    a = leaky(a); b = leaky(b);
    __nv_bfloat16 h, l;
    size_t base = (size_t)node * EMB;
    split1(a, h, l); g_x0h[base + 128 + j] = h; g_x0l[base + 128 + j] = l;
    split1(b, h, l); g_x0h[base + 256 + j] = h; g_x0l[base + 256 + j] = l;
}

// ---------------- edges / CSR ----------------
__device__ __forceinline__ void load_edge(const void* ei, int e, int& src, int& dst) {
    if (g_is64) {
        const long long* p = (const long long*)ei;
        src = (int)p[e]; dst = (int)p[EE + e];
    } else {
        const int* p = (const int*)ei;
        src = p[e]; dst = p[EE + e];
    }
}
__global__ void detect_idx_dtype(const void* ei) {
    const long long* p = (const long long*)ei;
    int ok64 = 1;
    for (int i = 0; i < 64; i++) {
        long long v = p[i];
        if (v < 0 || v >= NN) { ok64 = 0; break; }
    }
    g_is64 = ok64;
}
__global__ void zero_deg() {
    int i = blockIdx.x * blockDim.x + threadIdx.x;
    if (i < NN) g_deg[i] = 0;
}
__global__ void deg_count(const void* __restrict__ ei) {
    int e = blockIdx.x * blockDim.x + threadIdx.x;
    if (e < EE) { int s, d; load_edge(ei, e, s, d); atomicAdd(&g_deg[d], 1); }
}

#define SCAN_BLKS ((NN + 255) / 256)   // 196
__global__ void scan_phase1() {
    __shared__ int ws[8];
    int i = blockIdx.x * 256 + threadIdx.x;
    int lane = threadIdx.x & 31, wd = threadIdx.x >> 5;
    int v = (i < NN) ? g_deg[i] : 0;
    int s = v;
#pragma unroll
    for (int o = 1; o < 32; o <<= 1) {
        int t = __shfl_up_sync(0xffffffffu, s, o);
        if (lane >= o) s += t;
    }
    if (lane == 31) ws[wd] = s;
    __syncthreads();
    if (wd == 0) {
        int u = (lane < 8) ? ws[lane] : 0;
        int ss = u;
#pragma unroll
        for (int o = 1; o < 8; o <<= 1) {
            int t = __shfl_up_sync(0xffffffffu, ss, o);
            if (lane >= o) ss += t;
        }
        if (lane < 8) ws[lane] = ss;
    }
    __syncthreads();
    int incl = s + (wd ? ws[wd - 1] : 0);
    if (i < NN) g_scan[i] = incl;
    if (threadIdx.x == 255) g_bsum[blockIdx.x] = incl;
}
__global__ void scan_phase2() {
    __shared__ int ws[8];
    int t = threadIdx.x;
    int lane = t & 31, wd = t >> 5;
    int v = (t < SCAN_BLKS) ? g_bsum[t] : 0;
    int s = v;
#pragma unroll
    for (int o = 1; o < 32; o <<= 1) {
        int u = __shfl_up_sync(0xffffffffu, s, o);
        if (lane >= o) s += u;
    }
    if (lane == 31) ws[wd] = s;
    __syncthreads();
    if (wd == 0) {
        int u = (lane < 8) ? ws[lane] : 0;
        int ss = u;
#pragma unroll
        for (int o = 1; o < 8; o <<= 1) {
            int x = __shfl_up_sync(0xffffffffu, ss, o);
            if (lane >= o) ss += x;
        }
        if (lane < 8) ws[lane] = ss;
    }
    __syncthreads();
    int incl = s + (wd ? ws[wd - 1] : 0);
    if (t < SCAN_BLKS) g_boff[t] = incl - v;
}
__global__ void scan_phase3() {
    int i = blockIdx.x * 256 + threadIdx.x;
    if (i >= NN) return;
    int incl = g_scan[i] + g_boff[blockIdx.x];
    int d = g_deg[i];
    int beg = incl - d;
    g_rowptr[i] = beg;
    g_cursor[i] = beg;
    g_dinv[i] = rsqrtf((float)d + 1.0f);
    if (i == NN - 1) g_rowptr[NN] = incl;
}

__global__ void csr_fill(const void* __restrict__ ei) {
    int e = blockIdx.x * blockDim.x + threadIdx.x;
    if (e < EE) {
        int s, d; load_edge(ei, e, s, d);
        int pos = atomicAdd(&g_cursor[d], 1);
        g_csr[pos] = s;
    }
}

// ---------------- fused gather-aggregate (fp16 y) + combine + split ----------------
__global__ __launch_bounds__(256) void gcn_agg(
    const __half* __restrict__ y, const float* __restrict__ bias,
    __nv_bfloat16* __restrict__ oh, __nv_bfloat16* __restrict__ ol)
{
    int warp = (blockIdx.x * blockDim.x + threadIdx.x) >> 5;
    int lane = threadIdx.x & 31;
    if (warp >= NN) return;
    int beg = g_rowptr[warp], end = g_rowptr[warp + 1];

    float acc[12];
#pragma unroll
    for (int q = 0; q < 12; q++) acc[q] = 0.0f;

    for (int base = beg; base < end; base += 32) {
        int cnt = min(32, end - base);
        int s = (lane < cnt) ? g_csr[base + lane] : 0;
        for (int j = 0; j < cnt; j++) {
            int sj = __shfl_sync(0xffffffffu, s, j);
            const uint2* ys = (const uint2*)(y + (size_t)sj * EMB);
#pragma unroll
            for (int q = 0; q < 3; q++) {
                uint2 u = ys[lane + q * 32];
                float2 f0 = __half22float2(*(__half2*)&u.x);
                float2 f1 = __half22float2(*(__half2*)&u.y);
                acc[q * 4 + 0] += f0.x; acc[q * 4 + 1] += f0.y;
                acc[q * 4 + 2] += f1.x; acc[q * 4 + 3] += f1.y;
            }
        }
    }
    // self term
    {
        const uint2* yn = (const uint2*)(y + (size_t)warp * EMB);
#pragma unroll
        for (int q = 0; q < 3; q++) {
            uint2 u = yn[lane + q * 32];
            float2 f0 = __half22float2(*(__half2*)&u.x);
            float2 f1 = __half22float2(*(__half2*)&u.y);
            acc[q * 4 + 0] += f0.x; acc[q * 4 + 1] += f0.y;
            acc[q * 4 + 2] += f1.x; acc[q * 4 + 3] += f1.y;
        }
    }

    float dv = g_dinv[warp];
    const float4* bv = (const float4*)bias;
    uint2* ohp = (uint2*)(oh + (size_t)warp * EMB);
    uint2* olp = (uint2*)(ol + (size_t)warp * EMB);
#pragma unroll
    for (int q = 0; q < 3; q++) {
        float4 b = bv[lane + q * 32];
        float r0 = fmaf(dv, acc[q * 4 + 0], b.x);
        float r1 = fmaf(dv, acc[q * 4 + 1], b.y);
        float r2 = fmaf(dv, acc[q * 4 + 2], b.z);
        float r3 = fmaf(dv, acc[q * 4 + 3], b.w);
        __nv_bfloat16 h0, h1, h2, h3, l0, l1, l2, l3;
        split1(r0, h0, l0); split1(r1, h1, l1); split1(r2, h2, l2); split1(r3, h3, l3);
        uint2 uh; uh.x = packb(h0, h1); uh.y = packb(h2, h3);
        uint2 ul; ul.x = packb(l0, l1); ul.y = packb(l2, l3);
        ohp[lane + q * 32] = uh;
        olp[lane + q * 32] = ul;
    }
}

// ---------------- output init with bias ----------------
__global__ void init_out(float* __restrict__ out, const float* __restrict__ b) {
    int i = blockIdx.x * blockDim.x + threadIdx.x;
    if (i < NN) {
        out[i * 2 + 0] = b[0];
        out[i * 2 + 1] = b[1];
    }
}

// ---------------- host orchestration ----------------
extern "C" void kernel_launch(void* const* d_in, const int* in_sizes, int n_in,
                              void* d_out, int out_size)
{
    const float* des  = (const float*)d_in[0];
    const float* nump = (const float*)d_in[2];
    const float* catp = (const float*)d_in[3];
    const void*  ei   = d_in[4];
    const float* W_des = (const float*)d_in[5];  const float* b_des = (const float*)d_in[6];
    const float* W_num = (const float*)d_in[7];  const float* b_num = (const float*)d_in[8];
    const float* W_cat = (const float*)d_in[9];  const float* b_cat = (const float*)d_in[10];
    const float* W_in  = (const float*)d_in[11]; const float* b_in  = (const float*)d_in[12];
    const float* W_g1  = (const float*)d_in[13]; const float* b_g1  = (const float*)d_in[14];
    const float* W_g2  = (const float*)d_in[15]; const float* b_g2  = (const float*)d_in[16];
    const float* W_o1  = (const float*)d_in[17]; const float* b_o1  = (const float*)d_in[18];
    const float* W_o2  = (const float*)d_in[19]; const float* b_o2  = (const float*)d_in[20];
    float* out = (float*)d_out;

    __half* h;
    __nv_bfloat16 *desh, *desl, *x0h, *x0l, *x1h, *x1l, *wh, *wl;
    cudaGetSymbolAddress((void**)&h,    g_h);
    cudaGetSymbolAddress((void**)&desh, g_desh);
    cudaGetSymbolAddress((void**)&desl, g_desl);
    cudaGetSymbolAddress((void**)&x0h,  g_x0h);
    cudaGetSymbolAddress((void**)&x0l,  g_x0l);
    cudaGetSymbolAddress((void**)&x1h,  g_x1h);
    cudaGetSymbolAddress((void**)&x1l,  g_x1l);
    cudaGetSymbolAddress((void**)&wh,   g_wh);
    cudaGetSymbolAddress((void**)&wl,   g_wl);

    cudaFuncSetAttribute(gemm_hmma<true, true, false, false, true, false>,
                         cudaFuncAttributeMaxDynamicSharedMemorySize, GEMM_SMEM);
    cudaFuncSetAttribute(gemm_hmma<false, false, true, true, false, false>,
                         cudaFuncAttributeMaxDynamicSharedMemorySize, GEMM_SMEM);
    cudaFuncSetAttribute(gemm_hmma<true, true, false, false, false, true>,
                         cudaFuncAttributeMaxDynamicSharedMemorySize, GEMM_SMEM);

    const int MB = (NN + 127) / 128;   // 391
    dim3 blk(256);

    // launch order arranged so ncu (-s 5 -c 1) captures the des GEMM (index 5)
    split_f32<<<(NN * DESK / 4 + 255) / 256, blk>>>(des, desh, desl, NN * DESK / 4);      // 0
    wsplitT<<<(DESK * 128 + 255) / 256, blk>>>(W_des, DESK, 128, wh + WOFF_DES, wl + WOFF_DES); // 1
    wsplitT<<<(EMB * EMB + 255) / 256, blk>>>(W_in, EMB, EMB, wh + WOFF_IN, wl + WOFF_IN);      // 2
    wsplitT<<<(EMB * EMB + 255) / 256, blk>>>(W_g1, EMB, EMB, wh + WOFF_G1, wl + WOFF_G1);      // 3
    wsplitT<<<(EMB * EMB + 255) / 256, blk>>>(W_g2, EMB, EMB, wh + WOFF_G2, wl + WOFF_G2);      // 4
    gemm_hmma<true, true, false, false, true, false><<<dim3(1, MB), blk, GEMM_SMEM>>>(          // 5: PROFILED
        desh, desl, DESK, wh + WOFF_DES, wl + WOFF_DES, b_des,
        nullptr, x0h, x0l, EMB, NN, nullptr, nullptr);
    wsplitT<<<(EMB * EMB + 255) / 256, blk>>>(W_o1, EMB, EMB, wh + WOFF_O1, wl + WOFF_O1);
    front_small<<<NN, 128>>>(nump, catp, W_num, b_num, W_cat, b_cat);

    // edge preprocessing
    detect_idx_dtype<<<1, 1>>>(ei);
    zero_deg<<<(NN + 255) / 256, blk>>>();
    deg_count<<<(EE + 255) / 256, blk>>>(ei);
    scan_phase1<<<SCAN_BLKS, 256>>>();
    scan_phase2<<<1, 256>>>();
    scan_phase3<<<SCAN_BLKS, 256>>>();
    csr_fill<<<(EE + 255) / 256, blk>>>(ei);

    // x1 = leaky(x0 @ W_in + b_in)
    gemm_hmma<true, true, false, false, true, false><<<dim3(3, MB), blk, GEMM_SMEM>>>(
        x0h, x0l, EMB, wh + WOFF_IN, wl + WOFF_IN, b_in,
        nullptr, x1h, x1l, EMB, NN, nullptr, nullptr);

    // ---- GCN conv 1 ----
    gemm_hmma<false, false, true, true, false, false><<<dim3(3, MB), blk, GEMM_SMEM>>>(
        x1h, x1l, EMB, wh + WOFF_G1, wl + WOFF_G1, nullptr,
        h, nullptr, nullptr, EMB, NN, nullptr, nullptr);
    gcn_agg<<<(NN * 32 + 255) / 256, blk>>>(h, b_g1, x1h, x1l);

    // ---- GCN conv 2 ----
    gemm_hmma<false, false, true, true, false, false><<<dim3(3, MB), blk, GEMM_SMEM>>>(
        x1h, x1l, EMB, wh + WOFF_G2, wl + WOFF_G2, nullptr,
        h, nullptr, nullptr, EMB, NN, nullptr, nullptr);
    gcn_agg<<<(NN * 32 + 255) / 256, blk>>>(h, b_g2, x1h, x1l);

    // fused: out = leaky(x @ W_o1 + b_o1) @ W_o2 + b_o2
    init_out<<<(NN + 255) / 256, blk>>>(out, b_o2);
    gemm_hmma<true, true, false, false, false, true><<<dim3(3, MB), blk, GEMM_SMEM>>>(
        x1h, x1l, EMB, wh + WOFF_O1, wl + WOFF_O1, b_o1,
        nullptr, nullptr, nullptr, EMB, NN, W_o2, out);
}

// round 10
// speedup vs baseline: 3.1582x; 1.4773x over previous
#include <cuda_runtime.h>
#include <cuda_fp16.h>
#include <stdint.h>

#define NN   50000
#define EE   800000
#define EMB  384
#define DESK 768

// ---------------- scratch (no allocations allowed) ----------------
__device__ __align__(16) __half g_h[NN * EMB];      // fp16 message rows
__device__ float g_dinv[NN];
__device__ int   g_deg[NN];
__device__ int   g_rowptr[NN + 1];
__device__ int   g_cursor[NN];
__device__ int   g_csr[EE];
__device__ int   g_scan[NN];
__device__ int   g_bsum[256];
__device__ int   g_boff[256];
__device__ int   g_is64;

__device__ __align__(16) __half g_desh[NN * DESK];
__device__ __align__(16) __half g_desl[NN * DESK];
__device__ __align__(16) __half g_x0h[NN * EMB];
__device__ __align__(16) __half g_x0l[NN * EMB];
__device__ __align__(16) __half g_x1h[NN * EMB];
__device__ __align__(16) __half g_x1l[NN * EMB];

#define WTOT 688128
__device__ __align__(16) __half g_w[WTOT];          // weights: single fp16, transposed
enum { WOFF_DES = 0, WOFF_IN = 98304, WOFF_G1 = 245760, WOFF_G2 = 393216, WOFF_O1 = 540672 };

__device__ __forceinline__ float leaky(float v) { return v > 0.0f ? v : 0.01f * v; }

__device__ __forceinline__ void split1h(float v, __half& h, __half& l) {
    h = __float2half_rn(v);
    l = __float2half_rn(v - __half2float(h));
}
__device__ __forceinline__ uint32_t packh(__half a, __half b) {
    __half2 t = __halves2half2(a, b);
    return *(uint32_t*)&t;
}

// ---------------- low-level helpers ----------------
__device__ __forceinline__ uint32_t smem_u32(const void* p) {
    uint32_t a;
    asm("{ .reg .u64 t; cvta.to.shared.u64 t, %1; cvt.u32.u64 %0, t; }" : "=r"(a) : "l"(p));
    return a;
}
__device__ __forceinline__ void cp_async16(uint32_t dst, const void* src) {
    asm volatile("cp.async.cg.shared.global [%0], [%1], 16;" :: "r"(dst), "l"(src));
}
__device__ __forceinline__ void cp_commit() { asm volatile("cp.async.commit_group;" ::: "memory"); }
__device__ __forceinline__ void cp_wait_all() { asm volatile("cp.async.wait_group 0;" ::: "memory"); }
__device__ __forceinline__ void cp_wait_1()  { asm volatile("cp.async.wait_group 1;" ::: "memory"); }

// m16n8k16 fp16 MMA, fp32 accumulate
__device__ __forceinline__ void mma16816(float& d0, float& d1, float& d2, float& d3,
                                         uint32_t a0, uint32_t a1, uint32_t a2, uint32_t a3,
                                         uint32_t b0, uint32_t b1)
{
    asm volatile(
        "mma.sync.aligned.m16n8k16.row.col.f32.f16.f16.f32 "
        "{%0,%1,%2,%3}, {%4,%5,%6,%7}, {%8,%9}, {%0,%1,%2,%3};"
        : "+f"(d0), "+f"(d1), "+f"(d2), "+f"(d3)
        : "r"(a0), "r"(a1), "r"(a2), "r"(a3), "r"(b0), "r"(b1));
}
__device__ __forceinline__ void ldsm4(uint32_t& r0, uint32_t& r1, uint32_t& r2, uint32_t& r3,
                                      uint32_t addr)
{
    asm volatile("ldmatrix.sync.aligned.m8n8.x4.shared.b16 {%0,%1,%2,%3}, [%4];"
                 : "=r"(r0), "=r"(r1), "=r"(r2), "=r"(r3) : "r"(addr));
}

// ---------------- fp16-split HMMA GEMM: D = (Ah+Al) @ B^T ----------------
// A row-major [M,K] fp16 hi/lo; B row-major [N,K] fp16 single.
// SMEM per stage: Ah | Al | B, each 128 rows x 32 fp16, pitch 80B.
#define ROW_PITCH 80
#define TILE_B    (128 * ROW_PITCH)      // 10240
#define STAGE_B   (3 * TILE_B)           // 30720
#define GEMM_SMEM (2 * STAGE_B)          // 61440

template<bool LEAKY_F, bool BIAS_F, bool SCALE_F, bool WHALF, bool WSPLIT, bool FUSE>
__global__ __launch_bounds__(256) void gemm_hmma(
    const __half* __restrict__ Ah, const __half* __restrict__ Al, int K,
    const __half* __restrict__ B,
    const float* __restrict__ bias,
    __half* __restrict__ Cf, __half* __restrict__ Ch, __half* __restrict__ Cl,
    int ldc, int M,
    const float* __restrict__ Wo2, float* __restrict__ Out)
{
    extern __shared__ char smem[];
    const uint32_t sb = smem_u32(smem);
    const int tid  = threadIdx.x;
    const int wid  = tid >> 5;
    const int lane = tid & 31;
    const int g    = lane >> 2;
    const int tig  = lane & 3;
    const int warp_m = wid >> 2;
    const int warp_n = wid & 3;
    const int block_row = blockIdx.y * 128;
    const int block_col = blockIdx.x * 128;

    const __half* bases[3] = { Ah, Al, B };

    float acc[4][4][4];
#pragma unroll
    for (int mt = 0; mt < 4; mt++)
#pragma unroll
        for (int nt = 0; nt < 4; nt++)
#pragma unroll
            for (int q = 0; q < 4; q++) acc[mt][nt][q] = 0.0f;

    const int NC = K >> 5;

    // stage loader: 3 tiles x 128 rows x 4 granules = 1536 granules / 256 thr = 6 each
    auto load_stage = [&](int c, int s) {
        const uint32_t stage = sb + s * STAGE_B;
        const int kbyte = c * 64;
#pragma unroll
        for (int i = 0; i < 6; i++) {
            int gi   = tid + i * 256;
            int tile = gi >> 9;            // 0..2
            int r    = (gi >> 2) & 127;
            int c16  = gi & 3;
            int grow;
            if (tile < 2) { grow = block_row + r; if (grow >= M) grow = M - 1; }
            else          { grow = block_col + r; }
            const char* src = (const char*)bases[tile] + (size_t)grow * K * 2 + kbyte + c16 * 16;
            cp_async16(stage + tile * TILE_B + r * ROW_PITCH + c16 * 16, src);
        }
        cp_commit();
    };

    const uint32_t aOff = (uint32_t)(warp_m * 64 + (lane & 15)) * ROW_PITCH + (lane >> 4) * 16;
    const uint32_t bOff = 2 * TILE_B
                        + (uint32_t)(warp_n * 32 + (lane & 7) + ((lane >> 4) * 8)) * ROW_PITCH
                        + ((lane >> 3) & 1) * 16;

    load_stage(0, 0);

    for (int c = 0; c < NC; c++) {
        if (c + 1 < NC) { load_stage(c + 1, (c + 1) & 1); cp_wait_1(); }
        else            { cp_wait_all(); }
        __syncthreads();

        const uint32_t stage = sb + (c & 1) * STAGE_B;
        const uint32_t aBase = stage + aOff;
        const uint32_t bBase = stage + bOff;

#pragma unroll
        for (int kk = 0; kk < 32; kk += 16) {
            const uint32_t ko = kk * 2;
            uint32_t af[2][4][4];
#pragma unroll
            for (int arr = 0; arr < 2; arr++)
#pragma unroll
                for (int mt = 0; mt < 4; mt++)
                    ldsm4(af[arr][mt][0], af[arr][mt][1], af[arr][mt][2], af[arr][mt][3],
                          aBase + arr * TILE_B + mt * (16 * ROW_PITCH) + ko);

            uint32_t bf[4][2];
#pragma unroll
            for (int p = 0; p < 2; p++)
                ldsm4(bf[2 * p][0], bf[2 * p][1], bf[2 * p + 1][0], bf[2 * p + 1][1],
                      bBase + p * (16 * ROW_PITCH) + ko);

#pragma unroll
            for (int mt = 0; mt < 4; mt++)
#pragma unroll
                for (int nt = 0; nt < 4; nt++) {
                    float* d = acc[mt][nt];
                    mma16816(d[0], d[1], d[2], d[3],
                             af[0][mt][0], af[0][mt][1], af[0][mt][2], af[0][mt][3],
                             bf[nt][0], bf[nt][1]);                       // Ah*B
                    mma16816(d[0], d[1], d[2], d[3],
                             af[1][mt][0], af[1][mt][1], af[1][mt][2], af[1][mt][3],
                             bf[nt][0], bf[nt][1]);                       // Al*B
                }
        }
        __syncthreads();
    }

    if (FUSE) {
#pragma unroll
        for (int mt = 0; mt < 4; mt++) {
#pragma unroll
            for (int half = 0; half < 2; half++) {
                int row = block_row + warp_m * 64 + mt * 16 + g + half * 8;
                if (row < M) {
                    float s0 = 0.f, s1 = 0.f;
#pragma unroll
                    for (int nt = 0; nt < 4; nt++) {
                        int col = block_col + warp_n * 32 + nt * 8 + 2 * tig;
                        float v0 = acc[mt][nt][half * 2 + 0] + bias[col];
                        float v1 = acc[mt][nt][half * 2 + 1] + bias[col + 1];
                        v0 = leaky(v0); v1 = leaky(v1);
                        s0 += v0 * Wo2[col * 2 + 0] + v1 * Wo2[(col + 1) * 2 + 0];
                        s1 += v0 * Wo2[col * 2 + 1] + v1 * Wo2[(col + 1) * 2 + 1];
                    }
                    s0 += __shfl_xor_sync(0xffffffffu, s0, 1);
                    s0 += __shfl_xor_sync(0xffffffffu, s0, 2);
                    s1 += __shfl_xor_sync(0xffffffffu, s1, 1);
                    s1 += __shfl_xor_sync(0xffffffffu, s1, 2);
                    if (tig == 0) {
                        atomicAdd(&Out[row * 2 + 0], s0);
                        atomicAdd(&Out[row * 2 + 1], s1);
                    }
                }
            }
        }
    } else {
#pragma unroll
        for (int mt = 0; mt < 4; mt++) {
#pragma unroll
            for (int nt = 0; nt < 4; nt++) {
                int row0 = block_row + warp_m * 64 + mt * 16 + g;
                int row1 = row0 + 8;
                int col  = block_col + warp_n * 32 + nt * 8 + 2 * tig;
                float b0 = 0.f, b1 = 0.f;
                if (BIAS_F) { b0 = bias[col]; b1 = bias[col + 1]; }
#pragma unroll
                for (int half = 0; half < 2; half++) {
                    int row = half ? row1 : row0;
                    if (row < M) {
                        float v0 = acc[mt][nt][half * 2 + 0];
                        float v1 = acc[mt][nt][half * 2 + 1];
                        if (BIAS_F)  { v0 += b0; v1 += b1; }
                        if (LEAKY_F) { v0 = leaky(v0); v1 = leaky(v1); }
                        if (SCALE_F) { float dv = g_dinv[row]; v0 *= dv; v1 *= dv; }
                        size_t off = (size_t)row * ldc + col;
                        if (WHALF) *(__half2*)(Cf + off) = __floats2half2_rn(v0, v1);
                        if (WSPLIT) {
                            __half h0, h1, l0, l1;
                            split1h(v0, h0, l0); split1h(v1, h1, l1);
                            *(uint32_t*)(Ch + off) = packh(h0, h1);
                            *(uint32_t*)(Cl + off) = packh(l0, l1);
                        }
                    }
                }
            }
        }
    }
}

// ---------------- conversions ----------------
__global__ void split_f32(const float* __restrict__ x,
                          __half* __restrict__ h, __half* __restrict__ l, int n4)
{
    int i = blockIdx.x * blockDim.x + threadIdx.x;
    if (i >= n4) return;
    float4 v = ((const float4*)x)[i];
    __half h0, h1, h2, h3, l0, l1, l2, l3;
    split1h(v.x, h0, l0); split1h(v.y, h1, l1); split1h(v.z, h2, l2); split1h(v.w, h3, l3);
    uint2 uh; uh.x = packh(h0, h1); uh.y = packh(h2, h3);
    uint2 ul; ul.x = packh(l0, l1); ul.y = packh(l2, l3);
    ((uint2*)h)[i] = uh;
    ((uint2*)l)[i] = ul;
}

// W [K, Nn] fp32 -> out [Nn, K] fp16 (transpose, single precision level)
__global__ void wcvtT(const float* __restrict__ W, int K, int Nn, __half* __restrict__ o)
{
    int idx = blockIdx.x * blockDim.x + threadIdx.x;
    if (idx >= K * Nn) return;
    int k = idx / Nn, n = idx % Nn;
    o[(size_t)n * K + k] = __float2half_rn(W[idx]);
}

// ---------------- small front projections ----------------
__global__ void front_small(const float* __restrict__ nump, const float* __restrict__ catp,
                            const float* __restrict__ Wn, const float* __restrict__ bn,
                            const float* __restrict__ Wc, const float* __restrict__ bc)
{
    int node = blockIdx.x;
    int j = threadIdx.x;
    float n0 = nump[node * 4 + 0], n1 = nump[node * 4 + 1];
    float n2 = nump[node * 4 + 2], n3 = nump[node * 4 + 3];
    float c0 = catp[node * 3 + 0], c1 = catp[node * 3 + 1], c2 = catp[node * 3 + 2];

    float a = bn[j];
    a = fmaf(n0, Wn[0 * 128 + j], a); a = fmaf(n1, Wn[1 * 128 + j], a);
    a = fmaf(n2, Wn[2 * 128 + j], a); a = fmaf(n3, Wn[3 * 128 + j], a);
    float b = bc[j];
    b = fmaf(c0, Wc[0 * 128 + j], b); b = fmaf(c1, Wc[1 * 128 + j], b);
    b = fmaf(c2, Wc[2 * 128 + j], b);

    a = leaky(a); b = leaky(b);
    __half h, l;
    size_t base = (size_t)node * EMB;
    split1h(a, h, l); g_x0h[base + 128 + j] = h; g_x0l[base + 128 + j] = l;
    split1h(b, h, l); g_x0h[base + 256 + j] = h; g_x0l[base + 256 + j] = l;
}

// ---------------- edges / CSR ----------------
__device__ __forceinline__ void load_edge(const void* ei, int e, int& src, int& dst) {
    if (g_is64) {
        const long long* p = (const long long*)ei;
        src = (int)p[e]; dst = (int)p[EE + e];
    } else {
        const int* p = (const int*)ei;
        src = p[e]; dst = p[EE + e];
    }
}
__global__ void detect_idx_dtype(const void* ei) {
    const long long* p = (const long long*)ei;
    int ok64 = 1;
    for (int i = 0; i < 64; i++) {
        long long v = p[i];
        if (v < 0 || v >= NN) { ok64 = 0; break; }
    }
    g_is64 = ok64;
}
__global__ void zero_deg() {
    int i = blockIdx.x * blockDim.x + threadIdx.x;
    if (i < NN) g_deg[i] = 0;
}
__global__ void deg_count(const void* __restrict__ ei) {
    int e = blockIdx.x * blockDim.x + threadIdx.x;
    if (e < EE) { int s, d; load_edge(ei, e, s, d); atomicAdd(&g_deg[d], 1); }
}

#define SCAN_BLKS ((NN + 255) / 256)   // 196
__global__ void scan_phase1() {
    __shared__ int ws[8];
    int i = blockIdx.x * 256 + threadIdx.x;
    int lane = threadIdx.x & 31, wd = threadIdx.x >> 5;
    int v = (i < NN) ? g_deg[i] : 0;
    int s = v;
#pragma unroll
    for (int o = 1; o < 32; o <<= 1) {
        int t = __shfl_up_sync(0xffffffffu, s, o);
        if (lane >= o) s += t;
    }
    if (lane == 31) ws[wd] = s;
    __syncthreads();
    if (wd == 0) {
        int u = (lane < 8) ? ws[lane] : 0;
        int ss = u;
#pragma unroll
        for (int o = 1; o < 8; o <<= 1) {
            int t = __shfl_up_sync(0xffffffffu, ss, o);
            if (lane >= o) ss += t;
        }
        if (lane < 8) ws[lane] = ss;
    }
    __syncthreads();
    int incl = s + (wd ? ws[wd - 1] : 0);
    if (i < NN) g_scan[i] = incl;
    if (threadIdx.x == 255) g_bsum[blockIdx.x] = incl;
}
__global__ void scan_phase2() {
    __shared__ int ws[8];
    int t = threadIdx.x;
    int lane = t & 31, wd = t >> 5;
    int v = (t < SCAN_BLKS) ? g_bsum[t] : 0;
    int s = v;
#pragma unroll
    for (int o = 1; o < 32; o <<= 1) {
        int u = __shfl_up_sync(0xffffffffu, s, o);
        if (lane >= o) s += u;
    }
    if (lane == 31) ws[wd] = s;
    __syncthreads();
    if (wd == 0) {
        int u = (lane < 8) ? ws[lane] : 0;
        int ss = u;
#pragma unroll
        for (int o = 1; o < 8; o <<= 1) {
            int x = __shfl_up_sync(0xffffffffu, ss, o);
            if (lane >= o) ss += x;
        }
        if (lane < 8) ws[lane] = ss;
    }
    __syncthreads();
    int incl = s + (wd ? ws[wd - 1] : 0);
    if (t < SCAN_BLKS) g_boff[t] = incl - v;
}
__global__ void scan_phase3() {
    int i = blockIdx.x * 256 + threadIdx.x;
    if (i >= NN) return;
    int incl = g_scan[i] + g_boff[blockIdx.x];
    int d = g_deg[i];
    int beg = incl - d;
    g_rowptr[i] = beg;
    g_cursor[i] = beg;
    g_dinv[i] = rsqrtf((float)d + 1.0f);
    if (i == NN - 1) g_rowptr[NN] = incl;
}

__global__ void csr_fill(const void* __restrict__ ei) {
    int e = blockIdx.x * blockDim.x + threadIdx.x;
    if (e < EE) {
        int s, d; load_edge(ei, e, s, d);
        int pos = atomicAdd(&g_cursor[d], 1);
        g_csr[pos] = s;
    }
}

// ---------------- fused gather-aggregate (fp16 y) + combine + split ----------------
__global__ __launch_bounds__(256) void gcn_agg(
    const __half* __restrict__ y, const float* __restrict__ bias,
    __half* __restrict__ oh, __half* __restrict__ ol)
{
    int warp = (blockIdx.x * blockDim.x + threadIdx.x) >> 5;
    int lane = threadIdx.x & 31;
    if (warp >= NN) return;
    int beg = g_rowptr[warp], end = g_rowptr[warp + 1];

    float acc[12];
#pragma unroll
    for (int q = 0; q < 12; q++) acc[q] = 0.0f;

    for (int base = beg; base < end; base += 32) {
        int cnt = min(32, end - base);
        int s = (lane < cnt) ? g_csr[base + lane] : 0;
        for (int j = 0; j < cnt; j++) {
            int sj = __shfl_sync(0xffffffffu, s, j);
            const uint2* ys = (const uint2*)(y + (size_t)sj * EMB);
#pragma unroll
            for (int q = 0; q < 3; q++) {
                uint2 u = ys[lane + q * 32];
                float2 f0 = __half22float2(*(__half2*)&u.x);
                float2 f1 = __half22float2(*(__half2*)&u.y);
                acc[q * 4 + 0] += f0.x; acc[q * 4 + 1] += f0.y;
                acc[q * 4 + 2] += f1.x; acc[q * 4 + 3] += f1.y;
            }
        }
    }
    // self term
    {
        const uint2* yn = (const uint2*)(y + (size_t)warp * EMB);
#pragma unroll
        for (int q = 0; q < 3; q++) {
            uint2 u = yn[lane + q * 32];
            float2 f0 = __half22float2(*(__half2*)&u.x);
            float2 f1 = __half22float2(*(__half2*)&u.y);
            acc[q * 4 + 0] += f0.x; acc[q * 4 + 1] += f0.y;
            acc[q * 4 + 2] += f1.x; acc[q * 4 + 3] += f1.y;
        }
    }

    float dv = g_dinv[warp];
    const float4* bv = (const float4*)bias;
    uint2* ohp = (uint2*)(oh + (size_t)warp * EMB);
    uint2* olp = (uint2*)(ol + (size_t)warp * EMB);
#pragma unroll
    for (int q = 0; q < 3; q++) {
        float4 b = bv[lane + q * 32];
        float r0 = fmaf(dv, acc[q * 4 + 0], b.x);
        float r1 = fmaf(dv, acc[q * 4 + 1], b.y);
        float r2 = fmaf(dv, acc[q * 4 + 2], b.z);
        float r3 = fmaf(dv, acc[q * 4 + 3], b.w);
        __half h0, h1, h2, h3, l0, l1, l2, l3;
        split1h(r0, h0, l0); split1h(r1, h1, l1); split1h(r2, h2, l2); split1h(r3, h3, l3);
        uint2 uh; uh.x = packh(h0, h1); uh.y = packh(h2, h3);
        uint2 ul; ul.x = packh(l0, l1); ul.y = packh(l2, l3);
        ohp[lane + q * 32] = uh;
        olp[lane + q * 32] = ul;
    }
}

// ---------------- output init with bias ----------------
__global__ void init_out(float* __restrict__ out, const float* __restrict__ b) {
    int i = blockIdx.x * blockDim.x + threadIdx.x;
    if (i < NN) {
        out[i * 2 + 0] = b[0];
        out[i * 2 + 1] = b[1];
    }
}

// ---------------- host orchestration ----------------
extern "C" void kernel_launch(void* const* d_in, const int* in_sizes, int n_in,
                              void* d_out, int out_size)
{
    const float* des  = (const float*)d_in[0];
    const float* nump = (const float*)d_in[2];
    const float* catp = (const float*)d_in[3];
    const void*  ei   = d_in[4];
    const float* W_des = (const float*)d_in[5];  const float* b_des = (const float*)d_in[6];
    const float* W_num = (const float*)d_in[7];  const float* b_num = (const float*)d_in[8];
    const float* W_cat = (const float*)d_in[9];  const float* b_cat = (const float*)d_in[10];
    const float* W_in  = (const float*)d_in[11]; const float* b_in  = (const float*)d_in[12];
    const float* W_g1  = (const float*)d_in[13]; const float* b_g1  = (const float*)d_in[14];
    const float* W_g2  = (const float*)d_in[15]; const float* b_g2  = (const float*)d_in[16];
    const float* W_o1  = (const float*)d_in[17]; const float* b_o1  = (const float*)d_in[18];
    const float* W_o2  = (const float*)d_in[19]; const float* b_o2  = (const float*)d_in[20];
    float* out = (float*)d_out;

    __half *h, *desh, *desl, *x0h, *x0l, *x1h, *x1l, *w;
    cudaGetSymbolAddress((void**)&h,    g_h);
    cudaGetSymbolAddress((void**)&desh, g_desh);
    cudaGetSymbolAddress((void**)&desl, g_desl);
    cudaGetSymbolAddress((void**)&x0h,  g_x0h);
    cudaGetSymbolAddress((void**)&x0l,  g_x0l);
    cudaGetSymbolAddress((void**)&x1h,  g_x1h);
    cudaGetSymbolAddress((void**)&x1l,  g_x1l);
    cudaGetSymbolAddress((void**)&w,    g_w);

    cudaFuncSetAttribute(gemm_hmma<true, true, false, false, true, false>,
                         cudaFuncAttributeMaxDynamicSharedMemorySize, GEMM_SMEM);
    cudaFuncSetAttribute(gemm_hmma<false, false, true, true, false, false>,
                         cudaFuncAttributeMaxDynamicSharedMemorySize, GEMM_SMEM);
    cudaFuncSetAttribute(gemm_hmma<true, true, false, false, false, true>,
                         cudaFuncAttributeMaxDynamicSharedMemorySize, GEMM_SMEM);

    const int MB = (NN + 127) / 128;   // 391
    dim3 blk(256);

    // conversions
    split_f32<<<(NN * DESK / 4 + 255) / 256, blk>>>(des, desh, desl, NN * DESK / 4);
    wcvtT<<<(DESK * 128 + 255) / 256, blk>>>(W_des, DESK, 128, w + WOFF_DES);
    wcvtT<<<(EMB * EMB + 255) / 256, blk>>>(W_in, EMB, EMB, w + WOFF_IN);
    wcvtT<<<(EMB * EMB + 255) / 256, blk>>>(W_g1, EMB, EMB, w + WOFF_G1);
    wcvtT<<<(EMB * EMB + 255) / 256, blk>>>(W_g2, EMB, EMB, w + WOFF_G2);
    wcvtT<<<(EMB * EMB + 255) / 256, blk>>>(W_o1, EMB, EMB, w + WOFF_O1);

    // edge preprocessing
    detect_idx_dtype<<<1, 1>>>(ei);
    zero_deg<<<(NN + 255) / 256, blk>>>();
    deg_count<<<(EE + 255) / 256, blk>>>(ei);
    scan_phase1<<<SCAN_BLKS, 256>>>();
    scan_phase2<<<1, 256>>>();
    scan_phase3<<<SCAN_BLKS, 256>>>();
    csr_fill<<<(EE + 255) / 256, blk>>>(ei);

    // des projection -> x0[:, 0:128]
    gemm_hmma<true, true, false, false, true, false><<<dim3(1, MB), blk, GEMM_SMEM>>>(
        desh, desl, DESK, w + WOFF_DES, b_des,
        nullptr, x0h, x0l, EMB, NN, nullptr, nullptr);
    front_small<<<NN, 128>>>(nump, catp, W_num, b_num, W_cat, b_cat);

    // x1 = leaky(x0 @ W_in + b_in)
    gemm_hmma<true, true, false, false, true, false><<<dim3(3, MB), blk, GEMM_SMEM>>>(
        x0h, x0l, EMB, w + WOFF_IN, b_in,
        nullptr, x1h, x1l, EMB, NN, nullptr, nullptr);

    // ---- GCN conv 1 ----
    gemm_hmma<false, false, true, true, false, false><<<dim3(3, MB), blk, GEMM_SMEM>>>(
        x1h, x1l, EMB, w + WOFF_G1, nullptr,
        h, nullptr, nullptr, EMB, NN, nullptr, nullptr);
    gcn_agg<<<(NN * 32 + 255) / 256, blk>>>(h, b_g1, x1h, x1l);

    // ---- GCN conv 2 ----
    gemm_hmma<false, false, true, true, false, false><<<dim3(3, MB), blk, GEMM_SMEM>>>(
        x1h, x1l, EMB, w + WOFF_G2, nullptr,
        h, nullptr, nullptr, EMB, NN, nullptr, nullptr);
    gcn_agg<<<(NN * 32 + 255) / 256, blk>>>(h, b_g2, x1h, x1l);

    // fused: out = leaky(x @ W_o1 + b_o1) @ W_o2 + b_o2
    init_out<<<(NN + 255) / 256, blk>>>(out, b_o2);
    gemm_hmma<true, true, false, false, false, true><<<dim3(3, MB), blk, GEMM_SMEM>>>(
        x1h, x1l, EMB, w + WOFF_O1, b_o1,
        nullptr, nullptr, nullptr, EMB, NN, W_o2, out);
}